// round 1
// baseline (speedup 1.0000x reference)
#include <cuda_runtime.h>
#include <math.h>

#define BB     2
#define TT     2048
#define TE     2052
#define DIMM   1024
#define DD     64
#define NATTN  8
#define NKV    4
#define NSSM   8
#define SS     16
#define NMETA  4

// ---------------- scratch (device globals; no allocation allowed) ----------------
__device__ float g_xext[BB*TE*DIMM];        // (b, t_ext, 1024)
__device__ float g_wqkv[DIMM*DIMM];         // packed [512 q | 256 k | 256 v][1024]
__device__ float g_qkv [BB*TE*DIMM];        // gemm out, row=(b,t_ext)
__device__ float g_q   [BB*NATTN*TE*DD];    // normed+roped+gained q, head-major
__device__ float g_k   [BB*NKV*TE*DD];      // normed+roped k, head-major
__device__ float g_cat [BB*TT*DIMM];        // [attn(512) | ssm(512)]
__device__ float g_ssmx[BB*TT*NSSM*DD];     // (b,t,h,d)
__device__ float g_a   [BB*NSSM*TT*SS];     // (b,h,t,s)
__device__ float g_u   [BB*NSSM*TT*SS];
__device__ float g_cc  [BB*NSSM*TT*SS];
__device__ float g_hbuf[BB*NSSM*TT*SS];

// ---------------- x_ext = [meta ; x] ----------------
__global__ void xext_kernel(const float* __restrict__ x, const float* __restrict__ meta)
{
    int idx = blockIdx.x*256 + threadIdx.x;
    if (idx >= BB*TE*DIMM) return;
    int c  = idx % DIMM;
    int bt = idx / DIMM;
    int t  = bt % TE;
    int b  = bt / TE;
    g_xext[idx] = (t < NMETA) ? meta[t*DIMM + c]
                              : x[((size_t)(b*TT) + (t-NMETA))*DIMM + c];
}

// ---------------- pack [q(512) k(256) v(256)] weights ----------------
__global__ void packw_kernel(const float* __restrict__ qw, const float* __restrict__ kw,
                             const float* __restrict__ vw)
{
    int idx = blockIdx.x*256 + threadIdx.x;
    if (idx >= DIMM*DIMM) return;
    int r = idx >> 10, c = idx & 1023;
    float v;
    if (r < 512)      v = qw[r*DIMM + c];
    else if (r < 768) v = kw[(r-512)*DIMM + c];
    else              v = vw[(r-768)*DIMM + c];
    g_wqkv[idx] = v;
}

// ---------------- generic C[M,N] = A[M,K] @ B[N,K]^T, 64x64x16 tiles ----------------
__global__ void gemm_nt_kernel(const float* __restrict__ A, const float* __restrict__ B,
                               float* __restrict__ C, int M, int N, int K)
{
    __shared__ float As[16][64];
    __shared__ float Bs[16][64];
    const int tid = threadIdx.x;
    const int tx = tid & 15, ty = tid >> 4;
    const int m0 = blockIdx.y << 6, n0 = blockIdx.x << 6;
    const int lr = tid >> 2, lk = (tid & 3) << 2;

    float acc[4][4];
#pragma unroll
    for (int i = 0; i < 4; i++)
#pragma unroll
        for (int j = 0; j < 4; j++) acc[i][j] = 0.f;

    const bool am_ok = (m0 + lr) < M;
    const float* Ap = A + (size_t)(m0 + lr)*K + lk;
    const float* Bp = B + (size_t)(n0 + lr)*K + lk;

    for (int k0 = 0; k0 < K; k0 += 16) {
        float4 av = am_ok ? *(const float4*)(Ap + k0) : make_float4(0,0,0,0);
        float4 bv = *(const float4*)(Bp + k0);
        As[lk+0][lr]=av.x; As[lk+1][lr]=av.y; As[lk+2][lr]=av.z; As[lk+3][lr]=av.w;
        Bs[lk+0][lr]=bv.x; Bs[lk+1][lr]=bv.y; Bs[lk+2][lr]=bv.z; Bs[lk+3][lr]=bv.w;
        __syncthreads();
#pragma unroll
        for (int kk = 0; kk < 16; kk++) {
            float4 a = *(const float4*)&As[kk][ty<<2];
            float4 b = *(const float4*)&Bs[kk][tx<<2];
            acc[0][0]+=a.x*b.x; acc[0][1]+=a.x*b.y; acc[0][2]+=a.x*b.z; acc[0][3]+=a.x*b.w;
            acc[1][0]+=a.y*b.x; acc[1][1]+=a.y*b.y; acc[1][2]+=a.y*b.z; acc[1][3]+=a.y*b.w;
            acc[2][0]+=a.z*b.x; acc[2][1]+=a.z*b.y; acc[2][2]+=a.z*b.z; acc[2][3]+=a.z*b.w;
            acc[3][0]+=a.w*b.x; acc[3][1]+=a.w*b.y; acc[3][2]+=a.w*b.z; acc[3][3]+=a.w*b.w;
        }
        __syncthreads();
    }
#pragma unroll
    for (int i = 0; i < 4; i++) {
        int m = m0 + (ty<<2) + i;
        if (m < M) {
            float4 o = make_float4(acc[i][0], acc[i][1], acc[i][2], acc[i][3]);
            *(float4*)&C[(size_t)m*N + n0 + (tx<<2)] = o;
        }
    }
}

// ---------------- RMSNorm + RoPE (+q_gain), one warp per (b,head,t) row ----------------
__global__ void normrot_kernel(const float* __restrict__ qgain)
{
    const int QROWS = BB*NATTN*TE;
    const int KROWS = BB*NKV*TE;
    int gw = (blockIdx.x*blockDim.x + threadIdx.x) >> 5;
    int lane = threadIdx.x & 31;
    if (gw >= QROWS + KROWS) return;

    const float* src; float* dst; float gain; int t;
    if (gw < QROWS) {
        int b = gw / (NATTN*TE); int r = gw % (NATTN*TE); int h = r / TE; t = r % TE;
        src = &g_qkv[((size_t)(b*TE)+t)*DIMM + h*DD];
        dst = &g_q[(((size_t)(b*NATTN+h))*TE + t)*DD];
        gain = qgain[h];
    } else {
        int w2 = gw - QROWS;
        int b = w2 / (NKV*TE); int r = w2 % (NKV*TE); int h = r / TE; t = r % TE;
        src = &g_qkv[((size_t)(b*TE)+t)*DIMM + 512 + h*DD];
        dst = &g_k[(((size_t)(b*NKV+h))*TE + t)*DD];
        gain = 1.0f;
    }
    float x1 = src[lane], x2 = src[lane+32];
    float ss = x1*x1 + x2*x2;
#pragma unroll
    for (int o = 16; o > 0; o >>= 1) ss += __shfl_xor_sync(0xffffffffu, ss, o);
    float rinv = rsqrtf(ss*(1.0f/64.0f) + 1e-6f);
    x1 *= rinv; x2 *= rinv;
    // inv_freq = 10000^(-lane/32)
    float inv = expf(-(float)lane * 0.28782313662425575f);   // ln(10000)/32
    float f = (float)t * inv;
    float sn, cs; sincosf(f, &sn, &cs);
    dst[lane]    = (x1*cs - x2*sn) * gain;
    dst[lane+32] = (x1*sn + x2*cs) * gain;
}

// ---------------- causal flash attention, 64x64 tiles, online softmax ----------------
__global__ void attn_kernel(const float* __restrict__ attn_scale)
{
    extern __shared__ float sm[];
    float* Qs  = sm;             // [64][68]
    float* Ks  = sm + 64*68;
    float* Vs  = sm + 2*64*68;
    float* Ps  = sm + 3*64*68;
    float* mrow = sm + 4*64*68;  // [64]
    float* lrow = mrow + 64;
    float* arow = lrow + 64;

    const int b = blockIdx.z, h = blockIdx.y, qt = blockIdx.x;
    const int q0 = qt*64;
    const int hkv = h >> 1;          // repeat(k, 2) -> head h uses kv head h/2
    const int tid = threadIdx.x;
    const int tx = tid & 15, ty = tid >> 4;
    const int lr = tid >> 2;
    const int lc0 = (tid & 3) * 16;

    { // load Q tile
        int qrow = q0 + lr;
        const float* src = &g_q[(((size_t)(b*NATTN+h))*TE + qrow)*DD];
#pragma unroll
        for (int i = 0; i < 16; i += 4) {
            float4 v = make_float4(0,0,0,0);
            if (qrow < TE) v = *(const float4*)&src[lc0+i];
            *(float4*)&Qs[lr*68 + lc0 + i] = v;
        }
    }
    if (tid < 64) { mrow[tid] = -1e30f; lrow[tid] = 0.f; }

    float acc[4][4];
#pragma unroll
    for (int i = 0; i < 4; i++)
#pragma unroll
        for (int j = 0; j < 4; j++) acc[i][j] = 0.f;

    for (int kt = 0; kt <= qt; kt++) {
        const int k0 = kt*64;
        __syncthreads();   // previous tile fully consumed (and Q/stat init visible)
        { // load K,V tiles
            int krow = k0 + lr;
            const float* ksrc = &g_k[(((size_t)(b*NKV+hkv))*TE + krow)*DD];
            const float* vsrc = &g_qkv[((size_t)(b*TE)+krow)*DIMM + 768 + hkv*DD];
#pragma unroll
            for (int i = 0; i < 16; i += 4) {
                float4 kv = make_float4(0,0,0,0), vv = make_float4(0,0,0,0);
                if (krow < TE) { kv = *(const float4*)&ksrc[lc0+i]; vv = *(const float4*)&vsrc[lc0+i]; }
                *(float4*)&Ks[lr*68 + lc0 + i] = kv;
                *(float4*)&Vs[lr*68 + lc0 + i] = vv;
            }
        }
        __syncthreads();

        // S = Q K^T (each thread 4x4)
        float s[4][4];
#pragma unroll
        for (int i = 0; i < 4; i++)
#pragma unroll
            for (int j = 0; j < 4; j++) s[i][j] = 0.f;
#pragma unroll
        for (int kb = 0; kb < 64; kb += 4) {
            float4 qa[4], kb4[4];
#pragma unroll
            for (int i = 0; i < 4; i++) qa[i]  = *(const float4*)&Qs[((ty<<2)+i)*68 + kb];
#pragma unroll
            for (int j = 0; j < 4; j++) kb4[j] = *(const float4*)&Ks[((tx<<2)+j)*68 + kb];
#pragma unroll
            for (int i = 0; i < 4; i++)
#pragma unroll
                for (int j = 0; j < 4; j++)
                    s[i][j] += qa[i].x*kb4[j].x + qa[i].y*kb4[j].y
                             + qa[i].z*kb4[j].z + qa[i].w*kb4[j].w;
        }

        // mask + online softmax (rows owned by ty; 16-lane shfl groups)
#pragma unroll
        for (int i = 0; i < 4; i++) {
            int r = (ty<<2) + i;
            int q = q0 + r;
            float sv[4];
#pragma unroll
            for (int j = 0; j < 4; j++) {
                int kk = k0 + (tx<<2) + j;
                sv[j] = (kk <= q && kk < TE) ? s[i][j]*0.125f : -1e30f;
            }
            float tm = fmaxf(fmaxf(sv[0],sv[1]), fmaxf(sv[2],sv[3]));
#pragma unroll
            for (int o = 8; o > 0; o >>= 1) tm = fmaxf(tm, __shfl_xor_sync(0xffffffffu, tm, o));
            float mo = mrow[r];
            float mn = fmaxf(mo, tm);
            float p0 = __expf(sv[0]-mn), p1 = __expf(sv[1]-mn);
            float p2 = __expf(sv[2]-mn), p3 = __expf(sv[3]-mn);
            *(float4*)&Ps[r*68 + (tx<<2)] = make_float4(p0,p1,p2,p3);
            float ps = p0+p1+p2+p3;
#pragma unroll
            for (int o = 8; o > 0; o >>= 1) ps += __shfl_xor_sync(0xffffffffu, ps, o);
            if (tx == 0) {
                float al = __expf(mo - mn);
                arow[r] = al;
                lrow[r] = lrow[r]*al + ps;
                mrow[r] = mn;
            }
        }
        __syncthreads();

        // rescale + O += P V
#pragma unroll
        for (int i = 0; i < 4; i++) {
            float al = arow[(ty<<2)+i];
            acc[i][0]*=al; acc[i][1]*=al; acc[i][2]*=al; acc[i][3]*=al;
        }
#pragma unroll
        for (int kb = 0; kb < 64; kb += 4) {
            float4 v4[4];
#pragma unroll
            for (int kk = 0; kk < 4; kk++) v4[kk] = *(const float4*)&Vs[(kb+kk)*68 + (tx<<2)];
#pragma unroll
            for (int i = 0; i < 4; i++) {
                float4 p4 = *(const float4*)&Ps[((ty<<2)+i)*68 + kb];
                acc[i][0] += p4.x*v4[0].x + p4.y*v4[1].x + p4.z*v4[2].x + p4.w*v4[3].x;
                acc[i][1] += p4.x*v4[0].y + p4.y*v4[1].y + p4.z*v4[2].y + p4.w*v4[3].y;
                acc[i][2] += p4.x*v4[0].z + p4.y*v4[1].z + p4.z*v4[2].z + p4.w*v4[3].z;
                acc[i][3] += p4.x*v4[0].w + p4.y*v4[1].w + p4.z*v4[2].w + p4.w*v4[3].w;
            }
        }
    }
    __syncthreads();
    float ascale = attn_scale[0];
#pragma unroll
    for (int i = 0; i < 4; i++) {
        int q = q0 + (ty<<2) + i;
        if (q >= NMETA && q < TE) {
            float sc = ascale / lrow[(ty<<2)+i];
            float4 o = make_float4(acc[i][0]*sc, acc[i][1]*sc, acc[i][2]*sc, acc[i][3]*sc);
            *(float4*)&g_cat[((size_t)(b*TT) + (q-NMETA))*DIMM + h*DD + (tx<<2)] = o;
        }
    }
}

// ---------------- SSM: dt / Bx / Cc per (b,h,64-t tile) ----------------
__global__ void dtbc_kernel(const float* __restrict__ dtw, const float* __restrict__ dtb,
                            const float* __restrict__ Bw,  const float* __restrict__ Cw,
                            const float* __restrict__ logA)
{
    __shared__ float xs[64][65];
    __shared__ float ws[48][65];   // [dtw(16) | Bw(16) | Cw(16)]
    __shared__ float dts[64][16];
    const int b = blockIdx.z, h = blockIdx.y, t0 = blockIdx.x*64;
    const int tid = threadIdx.x;

    for (int idx = tid; idx < 48*64; idx += 256) {
        int o = idx >> 6, k = idx & 63;
        float v;
        if (o < 16)      v = dtw[(h*16+o)*64 + k];
        else if (o < 32) v = Bw[(h*16+(o-16))*64 + k];
        else             v = Cw[(h*16+(o-32))*64 + k];
        ws[o][k] = v;
    }
    for (int idx = tid; idx < 64*64; idx += 256) {
        int r = idx >> 6, k = idx & 63;
        xs[r][k] = g_ssmx[((size_t)(b*TT)+t0+r)*(NSSM*DD) + h*DD + k];
    }
    __syncthreads();

    const int r = tid >> 2;
    const size_t obase = (((size_t)(b*NSSM+h))*TT + t0 + r)*SS;

    { // phase 1: dt (4 outputs per thread) -> also write a = exp(clip(dt*A))
        int so = (tid & 3) << 2;
#pragma unroll
        for (int q = 0; q < 4; q++) {
            int o = so + q;
            float d = 0.f;
#pragma unroll
            for (int k = 0; k < 64; k++) d += xs[r][k]*ws[o][k];
            d += dtb[h*16 + o];
            float sp = (d > 20.f) ? d : log1pf(expf(d));
            float dt = fminf(sp, 1.0f);
            dts[r][o] = dt;
            float A  = fminf(-expf(logA[h*16 + o]), 10.0f);
            float la = fminf(fmaxf(dt*A, -0.5f), 0.0f);
            g_a[obase + o] = expf(la);
        }
    }
    __syncthreads();
    { // phase 2: Bx (u) and Cc (8 outputs per thread)
        int jo = (tid & 3) << 3;
#pragma unroll
        for (int q = 0; q < 8; q++) {
            int o2 = jo + q;       // 0..15 -> Bx, 16..31 -> Cc; ws row = 16+o2 both ways
            float d = 0.f;
#pragma unroll
            for (int k = 0; k < 64; k++) d += xs[r][k]*ws[16+o2][k];
            if (o2 < 16) g_u[obase + o2]        = d * dts[r][o2];
            else         g_cc[obase + (o2-16)]  = d;
        }
    }
}

// ---------------- sequential scan: h_t = a_t h_{t-1} + u_t, 256 lanes ----------------
__global__ void scan_kernel()
{
    int g = blockIdx.x*32 + threadIdx.x;   // 0..255
    int s = g & 15, hh = (g >> 4) & 7, b = g >> 7;
    size_t base = ((size_t)(b*NSSM+hh))*TT*SS + s;
    float hv = 0.f;
    for (int t = 0; t < TT; t++) {
        size_t o = base + (size_t)t*SS;
        hv = g_a[o]*hv + g_u[o];
        g_hbuf[o] = hv;
    }
}

// ---------------- SSM epilogue: out = h @ Ow^T + (Cc.h) * x0, scaled ----------------
__global__ void ssmout_kernel(const float* __restrict__ Ow, const float* __restrict__ ssm_scale)
{
    __shared__ float hs[64][17];
    __shared__ float cs[64][17];
    __shared__ float ows[64][17];
    const int b = blockIdx.z, h = blockIdx.y, t0 = blockIdx.x*64;
    const int tid = threadIdx.x;

    for (int idx = tid; idx < 64*16; idx += 256) {
        int r = idx >> 4, s = idx & 15;
        size_t src = (((size_t)(b*NSSM+h))*TT + t0 + r)*SS + s;
        hs[r][s] = g_hbuf[src];
        cs[r][s] = g_cc[src];
        ows[r][s] = Ow[(h*64 + r)*16 + s];   // r plays 'd' role here
    }
    __syncthreads();

    const int r = tid >> 2, dp = tid & 3;
    float y = 0.f;
#pragma unroll
    for (int s = 0; s < 16; s++) y += cs[r][s]*hs[r][s];
    float x0 = g_ssmx[((size_t)(b*TT)+t0+r)*(NSSM*DD) + h*DD];
    float sc = ssm_scale[0];
    float yx = y * x0;
#pragma unroll
    for (int q = 0; q < 16; q++) {
        int d = dp*16 + q;
        float v = yx;
#pragma unroll
        for (int s = 0; s < 16; s++) v += hs[r][s]*ows[d][s];
        g_cat[((size_t)(b*TT)+t0+r)*DIMM + 512 + h*DD + d] = v*sc;
    }
}

// ---------------- launch ----------------
extern "C" void kernel_launch(void* const* d_in, const int* in_sizes, int n_in,
                              void* d_out, int out_size)
{
    const float* x         = (const float*)d_in[0];
    const float* meta      = (const float*)d_in[1];
    const float* qw        = (const float*)d_in[2];
    const float* kw        = (const float*)d_in[3];
    const float* vw        = (const float*)d_in[4];
    const float* qgain     = (const float*)d_in[5];
    const float* ssm_in_w  = (const float*)d_in[6];
    const float* projw     = (const float*)d_in[7];
    const float* attn_sc   = (const float*)d_in[8];
    const float* ssm_sc    = (const float*)d_in[9];
    const float* logA      = (const float*)d_in[10];
    const float* Bw        = (const float*)d_in[11];
    const float* Cw        = (const float*)d_in[12];
    const float* dtw       = (const float*)d_in[13];
    const float* dtb       = (const float*)d_in[14];
    const float* Ow        = (const float*)d_in[15];
    float* out = (float*)d_out;

    float *p_xext, *p_wqkv, *p_qkv, *p_cat, *p_ssmx;
    cudaGetSymbolAddress((void**)&p_xext, g_xext);
    cudaGetSymbolAddress((void**)&p_wqkv, g_wqkv);
    cudaGetSymbolAddress((void**)&p_qkv,  g_qkv);
    cudaGetSymbolAddress((void**)&p_cat,  g_cat);
    cudaGetSymbolAddress((void**)&p_ssmx, g_ssmx);

    const int ATTN_SMEM = (4*64*68 + 3*64) * (int)sizeof(float);  // 70400 B
    cudaFuncSetAttribute(attn_kernel, cudaFuncAttributeMaxDynamicSharedMemorySize, ATTN_SMEM);

    xext_kernel<<<(BB*TE*DIMM + 255)/256, 256>>>(x, meta);
    packw_kernel<<<(DIMM*DIMM + 255)/256, 256>>>(qw, kw, vw);
    gemm_nt_kernel<<<dim3(DIMM/64, (BB*TE + 63)/64), 256>>>(p_xext, p_wqkv, p_qkv, BB*TE, DIMM, DIMM);
    {
        int warps = BB*(NATTN+NKV)*TE;
        normrot_kernel<<<(warps*32 + 255)/256, 256>>>(qgain);
    }
    gemm_nt_kernel<<<dim3((NSSM*DD)/64, (BB*TT)/64), 256>>>(x, ssm_in_w, p_ssmx, BB*TT, NSSM*DD, DIMM);
    attn_kernel<<<dim3((TE + 63)/64, NATTN, BB), 256, ATTN_SMEM>>>(attn_sc);
    dtbc_kernel<<<dim3(TT/64, NSSM, BB), 256>>>(dtw, dtb, Bw, Cw, logA);
    scan_kernel<<<8, 32>>>();
    ssmout_kernel<<<dim3(TT/64, NSSM, BB), 256>>>(Ow, ssm_sc);
    gemm_nt_kernel<<<dim3(DIMM/64, (BB*TT)/64), 256>>>(p_cat, projw, out, BB*TT, DIMM, DIMM);
}

// round 2
// speedup vs baseline: 1.1061x; 1.1061x over previous
#include <cuda_runtime.h>
#include <math.h>

#define BB     2
#define TT     2048
#define TE     2052
#define DIMM   1024
#define DD     64
#define NATTN  8
#define NKV    4
#define NSSM   8
#define SS     16
#define NMETA  4

typedef unsigned long long u64;

__device__ __forceinline__ u64 pk2(float lo, float hi) {
    u64 r; asm("mov.b64 %0, {%1, %2};" : "=l"(r) : "f"(lo), "f"(hi)); return r;
}
__device__ __forceinline__ void fma2(u64& d, u64 a, u64 b) {
    asm("fma.rn.f32x2 %0, %1, %2, %0;" : "+l"(d) : "l"(a), "l"(b));
}
__device__ __forceinline__ float2 up2(u64 v) {
    float2 r; asm("mov.b64 {%0, %1}, %2;" : "=f"(r.x), "=f"(r.y) : "l"(v)); return r;
}

// ---------------- scratch ----------------
__device__ float g_xext[BB*TE*DIMM];
__device__ float g_wqkv[DIMM*DIMM];
__device__ float g_qkv [BB*TE*DIMM];
__device__ float g_q   [BB*NATTN*TE*DD];
__device__ float g_k   [BB*NKV*TE*DD];
__device__ float g_cat [BB*TT*DIMM];
__device__ float g_ssmx[BB*TT*NSSM*DD];
__device__ float g_a   [BB*NSSM*TT*SS];
__device__ float g_u   [BB*NSSM*TT*SS];
__device__ float g_cc  [BB*NSSM*TT*SS];
__device__ float g_hbuf[BB*NSSM*TT*SS];

// ---------------- x_ext = [meta ; x] ----------------
__global__ void xext_kernel(const float* __restrict__ x, const float* __restrict__ meta)
{
    int idx = blockIdx.x*256 + threadIdx.x;
    if (idx >= BB*TE*DIMM) return;
    int c  = idx % DIMM;
    int bt = idx / DIMM;
    int t  = bt % TE;
    int b  = bt / TE;
    g_xext[idx] = (t < NMETA) ? meta[t*DIMM + c]
                              : x[((size_t)(b*TT) + (t-NMETA))*DIMM + c];
}

// ---------------- pack [q(512) k(256) v(256)] weights ----------------
__global__ void packw_kernel(const float* __restrict__ qw, const float* __restrict__ kw,
                             const float* __restrict__ vw)
{
    int idx = blockIdx.x*256 + threadIdx.x;
    if (idx >= DIMM*DIMM) return;
    int r = idx >> 10, c = idx & 1023;
    float v;
    if (r < 512)      v = qw[r*DIMM + c];
    else if (r < 768) v = kw[(r-512)*DIMM + c];
    else              v = vw[(r-768)*DIMM + c];
    g_wqkv[idx] = v;
}

// ---------------- C[M,N] = A[M,K] @ B[N,K]^T, 128x128x8, double-buffered, f32x2 ----------------
__global__ void __launch_bounds__(256) gemm128_kernel(const float* __restrict__ A,
                                                      const float* __restrict__ B,
                                                      float* __restrict__ C,
                                                      int M, int N, int K)
{
    __shared__ float As[2][8][128];
    __shared__ float Bs[2][8][128];
    const int tid = threadIdx.x;
    const int tx = tid & 15, ty = tid >> 4;
    const int m0 = blockIdx.y << 7, n0 = blockIdx.x << 7;
    const int lr = tid >> 1, lc = (tid & 1) << 2;
    const float* Ap = A + (size_t)(m0 + lr)*K + lc;
    const float* Bp = B + (size_t)(n0 + lr)*K + lc;
    const bool a_ok = (m0 + lr) < M;

    u64 acc2[8][4];
#pragma unroll
    for (int i = 0; i < 8; i++)
#pragma unroll
        for (int j = 0; j < 4; j++) acc2[i][j] = 0ull;

    {   // prologue: fill buffer 0
        float4 ar = a_ok ? *(const float4*)Ap : make_float4(0,0,0,0);
        float4 br = *(const float4*)Bp;
        As[0][lc+0][lr]=ar.x; As[0][lc+1][lr]=ar.y; As[0][lc+2][lr]=ar.z; As[0][lc+3][lr]=ar.w;
        Bs[0][lc+0][lr]=br.x; Bs[0][lc+1][lr]=br.y; Bs[0][lc+2][lr]=br.z; Bs[0][lc+3][lr]=br.w;
    }
    __syncthreads();

    for (int k0 = 0; k0 < K; k0 += 8) {
        const int p = (k0 >> 3) & 1;
        const bool pre = (k0 + 8) < K;
        float4 an, bn;
        if (pre) {
            an = a_ok ? *(const float4*)(Ap + k0 + 8) : make_float4(0,0,0,0);
            bn = *(const float4*)(Bp + k0 + 8);
        }
#pragma unroll
        for (int kk = 0; kk < 8; kk++) {
            const float* as = &As[p][kk][ty << 3];
            const float* bs = &Bs[p][kk][tx << 3];
            float4 aA = *(const float4*)as,      aB = *(const float4*)(as + 4);
            float4 bA = *(const float4*)bs,      bB = *(const float4*)(bs + 4);
            u64 b2[4] = { pk2(bA.x,bA.y), pk2(bA.z,bA.w), pk2(bB.x,bB.y), pk2(bB.z,bB.w) };
            float av[8] = {aA.x,aA.y,aA.z,aA.w,aB.x,aB.y,aB.z,aB.w};
#pragma unroll
            for (int i = 0; i < 8; i++) {
                u64 a2 = pk2(av[i], av[i]);
                fma2(acc2[i][0], a2, b2[0]);
                fma2(acc2[i][1], a2, b2[1]);
                fma2(acc2[i][2], a2, b2[2]);
                fma2(acc2[i][3], a2, b2[3]);
            }
        }
        if (pre) {
            const int q = p ^ 1;
            As[q][lc+0][lr]=an.x; As[q][lc+1][lr]=an.y; As[q][lc+2][lr]=an.z; As[q][lc+3][lr]=an.w;
            Bs[q][lc+0][lr]=bn.x; Bs[q][lc+1][lr]=bn.y; Bs[q][lc+2][lr]=bn.z; Bs[q][lc+3][lr]=bn.w;
        }
        __syncthreads();
    }

#pragma unroll
    for (int i = 0; i < 8; i++) {
        int m = m0 + (ty << 3) + i;
        if (m < M) {
            float2 c0 = up2(acc2[i][0]), c1 = up2(acc2[i][1]);
            float2 c2 = up2(acc2[i][2]), c3 = up2(acc2[i][3]);
            *(float4*)&C[(size_t)m*N + n0 + (tx<<3)]     = make_float4(c0.x,c0.y,c1.x,c1.y);
            *(float4*)&C[(size_t)m*N + n0 + (tx<<3) + 4] = make_float4(c2.x,c2.y,c3.x,c3.y);
        }
    }
}

// ---------------- RMSNorm + RoPE (+q_gain), one warp per (b,head,t) row ----------------
__global__ void normrot_kernel(const float* __restrict__ qgain)
{
    const int QROWS = BB*NATTN*TE;
    const int KROWS = BB*NKV*TE;
    int gw = (blockIdx.x*blockDim.x + threadIdx.x) >> 5;
    int lane = threadIdx.x & 31;
    if (gw >= QROWS + KROWS) return;

    const float* src; float* dst; float gain; int t;
    if (gw < QROWS) {
        int b = gw / (NATTN*TE); int r = gw % (NATTN*TE); int h = r / TE; t = r % TE;
        src = &g_qkv[((size_t)(b*TE)+t)*DIMM + h*DD];
        dst = &g_q[(((size_t)(b*NATTN+h))*TE + t)*DD];
        gain = qgain[h];
    } else {
        int w2 = gw - QROWS;
        int b = w2 / (NKV*TE); int r = w2 % (NKV*TE); int h = r / TE; t = r % TE;
        src = &g_qkv[((size_t)(b*TE)+t)*DIMM + 512 + h*DD];
        dst = &g_k[(((size_t)(b*NKV+h))*TE + t)*DD];
        gain = 1.0f;
    }
    float x1 = src[lane], x2 = src[lane+32];
    float ss = x1*x1 + x2*x2;
#pragma unroll
    for (int o = 16; o > 0; o >>= 1) ss += __shfl_xor_sync(0xffffffffu, ss, o);
    float rinv = rsqrtf(ss*(1.0f/64.0f) + 1e-6f);
    x1 *= rinv; x2 *= rinv;
    float inv = expf(-(float)lane * 0.28782313662425575f);   // ln(10000)/32
    float f = (float)t * inv;
    float sn, cs; sincosf(f, &sn, &cs);
    dst[lane]    = (x1*cs - x2*sn) * gain;
    dst[lane+32] = (x1*sn + x2*cs) * gain;
}

// ---------------- causal flash attention, 64x64 tiles, 128 threads, 8x4 micro ----------------
__global__ void __launch_bounds__(128) attn_kernel(const float* __restrict__ attn_scale)
{
    extern __shared__ float sm[];
    float* Qs  = sm;             // [64][68]
    float* Ks  = sm + 64*68;
    float* Vs  = sm + 2*64*68;
    float* Ps  = sm + 3*64*68;
    float* mrow = sm + 4*64*68;  // [64]
    float* lrow = mrow + 64;
    float* arow = lrow + 64;

    const int b = blockIdx.z, h = blockIdx.y, qt = blockIdx.x;
    const int q0 = qt << 6;
    const int hkv = h >> 1;
    const int tid = threadIdx.x;
    const int tx = tid & 15, ty = tid >> 4;      // ty 0..7 (8 q-rows each)
    const int lr = tid >> 1;                      // 0..63
    const int lc0 = (tid & 1) << 5;               // 0 or 32

    {   // load Q tile (8 float4 per thread)
        int qrow = q0 + lr;
        const float* src = &g_q[(((size_t)(b*NATTN+h))*TE + qrow)*DD];
#pragma unroll
        for (int i = 0; i < 32; i += 4) {
            float4 v = make_float4(0,0,0,0);
            if (qrow < TE) v = *(const float4*)&src[lc0+i];
            *(float4*)&Qs[lr*68 + lc0 + i] = v;
        }
    }
    if (tid < 64) { mrow[tid] = -1e30f; lrow[tid] = 0.f; }

    float acc[8][4];
#pragma unroll
    for (int i = 0; i < 8; i++)
#pragma unroll
        for (int j = 0; j < 4; j++) acc[i][j] = 0.f;

    for (int kt = 0; kt <= qt; kt++) {
        const int k0 = kt << 6;
        __syncthreads();   // previous tile fully consumed
        {   // load K,V tiles
            int krow = k0 + lr;
            const float* ksrc = &g_k[(((size_t)(b*NKV+hkv))*TE + krow)*DD];
            const float* vsrc = &g_qkv[((size_t)(b*TE)+krow)*DIMM + 768 + hkv*DD];
#pragma unroll
            for (int i = 0; i < 32; i += 4) {
                float4 kv = make_float4(0,0,0,0), vv = make_float4(0,0,0,0);
                if (krow < TE) { kv = *(const float4*)&ksrc[lc0+i]; vv = *(const float4*)&vsrc[lc0+i]; }
                *(float4*)&Ks[lr*68 + lc0 + i] = kv;
                *(float4*)&Vs[lr*68 + lc0 + i] = vv;
            }
        }
        __syncthreads();

        // S = Q K^T (8x4 per thread)
        float s[8][4];
#pragma unroll
        for (int i = 0; i < 8; i++)
#pragma unroll
            for (int j = 0; j < 4; j++) s[i][j] = 0.f;
#pragma unroll
        for (int kb = 0; kb < 64; kb += 4) {
            float4 k4[4];
#pragma unroll
            for (int j = 0; j < 4; j++) k4[j] = *(const float4*)&Ks[((tx<<2)+j)*68 + kb];
#pragma unroll
            for (int i = 0; i < 8; i++) {
                float4 q4 = *(const float4*)&Qs[((ty<<3)+i)*68 + kb];
                s[i][0] += q4.x*k4[0].x + q4.y*k4[0].y + q4.z*k4[0].z + q4.w*k4[0].w;
                s[i][1] += q4.x*k4[1].x + q4.y*k4[1].y + q4.z*k4[1].z + q4.w*k4[1].w;
                s[i][2] += q4.x*k4[2].x + q4.y*k4[2].y + q4.z*k4[2].z + q4.w*k4[2].w;
                s[i][3] += q4.x*k4[3].x + q4.y*k4[3].y + q4.z*k4[3].z + q4.w*k4[3].w;
            }
        }

        // mask + online softmax
#pragma unroll
        for (int i = 0; i < 8; i++) {
            int r = (ty<<3) + i;
            int q = q0 + r;
            float sv[4];
#pragma unroll
            for (int j = 0; j < 4; j++) {
                int kk = k0 + (tx<<2) + j;
                sv[j] = (kk <= q) ? s[i][j]*0.125f : -1e30f;
            }
            float tm = fmaxf(fmaxf(sv[0],sv[1]), fmaxf(sv[2],sv[3]));
#pragma unroll
            for (int o = 8; o > 0; o >>= 1) tm = fmaxf(tm, __shfl_xor_sync(0xffffffffu, tm, o));
            float mo = mrow[r];
            float mn = fmaxf(mo, tm);
            float p0 = __expf(sv[0]-mn), p1 = __expf(sv[1]-mn);
            float p2 = __expf(sv[2]-mn), p3 = __expf(sv[3]-mn);
            *(float4*)&Ps[r*68 + (tx<<2)] = make_float4(p0,p1,p2,p3);
            float ps = p0+p1+p2+p3;
#pragma unroll
            for (int o = 8; o > 0; o >>= 1) ps += __shfl_xor_sync(0xffffffffu, ps, o);
            if (tx == 0) {
                float al = __expf(mo - mn);
                arow[r] = al;
                lrow[r] = lrow[r]*al + ps;
                mrow[r] = mn;
            }
        }
        __syncthreads();

        // rescale + O += P V
#pragma unroll
        for (int i = 0; i < 8; i++) {
            float al = arow[(ty<<3)+i];
            acc[i][0]*=al; acc[i][1]*=al; acc[i][2]*=al; acc[i][3]*=al;
        }
#pragma unroll
        for (int kb = 0; kb < 64; kb += 4) {
            float4 v4[4];
#pragma unroll
            for (int kk = 0; kk < 4; kk++) v4[kk] = *(const float4*)&Vs[(kb+kk)*68 + (tx<<2)];
#pragma unroll
            for (int i = 0; i < 8; i++) {
                float4 p4 = *(const float4*)&Ps[((ty<<3)+i)*68 + kb];
                acc[i][0] += p4.x*v4[0].x + p4.y*v4[1].x + p4.z*v4[2].x + p4.w*v4[3].x;
                acc[i][1] += p4.x*v4[0].y + p4.y*v4[1].y + p4.z*v4[2].y + p4.w*v4[3].y;
                acc[i][2] += p4.x*v4[0].z + p4.y*v4[1].z + p4.z*v4[2].z + p4.w*v4[3].z;
                acc[i][3] += p4.x*v4[0].w + p4.y*v4[1].w + p4.z*v4[2].w + p4.w*v4[3].w;
            }
        }
    }
    __syncthreads();
    float ascale = attn_scale[0];
#pragma unroll
    for (int i = 0; i < 8; i++) {
        int q = q0 + (ty<<3) + i;
        if (q >= NMETA && q < TE) {
            float sc = ascale / lrow[(ty<<3)+i];
            float4 o = make_float4(acc[i][0]*sc, acc[i][1]*sc, acc[i][2]*sc, acc[i][3]*sc);
            *(float4*)&g_cat[((size_t)(b*TT) + (q-NMETA))*DIMM + h*DD + (tx<<2)] = o;
        }
    }
}

// ---------------- SSM: dt / Bx / Cc per (b,h,64-t tile) ----------------
__global__ void dtbc_kernel(const float* __restrict__ dtw, const float* __restrict__ dtb,
                            const float* __restrict__ Bw,  const float* __restrict__ Cw,
                            const float* __restrict__ logA)
{
    __shared__ float xs[64][65];
    __shared__ float ws[48][65];
    __shared__ float dts[64][16];
    const int b = blockIdx.z, h = blockIdx.y, t0 = blockIdx.x*64;
    const int tid = threadIdx.x;

    for (int idx = tid; idx < 48*64; idx += 256) {
        int o = idx >> 6, k = idx & 63;
        float v;
        if (o < 16)      v = dtw[(h*16+o)*64 + k];
        else if (o < 32) v = Bw[(h*16+(o-16))*64 + k];
        else             v = Cw[(h*16+(o-32))*64 + k];
        ws[o][k] = v;
    }
    for (int idx = tid; idx < 64*64; idx += 256) {
        int r = idx >> 6, k = idx & 63;
        xs[r][k] = g_ssmx[((size_t)(b*TT)+t0+r)*(NSSM*DD) + h*DD + k];
    }
    __syncthreads();

    const int r = tid >> 2;
    const size_t obase = (((size_t)(b*NSSM+h))*TT + t0 + r)*SS;

    {
        int so = (tid & 3) << 2;
#pragma unroll
        for (int q = 0; q < 4; q++) {
            int o = so + q;
            float d = 0.f;
#pragma unroll
            for (int k = 0; k < 64; k++) d += xs[r][k]*ws[o][k];
            d += dtb[h*16 + o];
            float sp = (d > 20.f) ? d : log1pf(expf(d));
            float dt = fminf(sp, 1.0f);
            dts[r][o] = dt;
            float A  = fminf(-expf(logA[h*16 + o]), 10.0f);
            float la = fminf(fmaxf(dt*A, -0.5f), 0.0f);
            g_a[obase + o] = expf(la);
        }
    }
    __syncthreads();
    {
        int jo = (tid & 3) << 3;
#pragma unroll
        for (int q = 0; q < 8; q++) {
            int o2 = jo + q;
            float d = 0.f;
#pragma unroll
            for (int k = 0; k < 64; k++) d += xs[r][k]*ws[16+o2][k];
            if (o2 < 16) g_u[obase + o2]        = d * dts[r][o2];
            else         g_cc[obase + (o2-16)]  = d;
        }
    }
}

// ---------------- sequential scan ----------------
__global__ void scan_kernel()
{
    int g = blockIdx.x*32 + threadIdx.x;
    int s = g & 15, hh = (g >> 4) & 7, b = g >> 7;
    size_t base = ((size_t)(b*NSSM+hh))*TT*SS + s;
    float hv = 0.f;
    for (int t = 0; t < TT; t++) {
        size_t o = base + (size_t)t*SS;
        hv = g_a[o]*hv + g_u[o];
        g_hbuf[o] = hv;
    }
}

// ---------------- SSM epilogue ----------------
__global__ void ssmout_kernel(const float* __restrict__ Ow, const float* __restrict__ ssm_scale)
{
    __shared__ float hs[64][17];
    __shared__ float cs[64][17];
    __shared__ float ows[64][17];
    const int b = blockIdx.z, h = blockIdx.y, t0 = blockIdx.x*64;
    const int tid = threadIdx.x;

    for (int idx = tid; idx < 64*16; idx += 256) {
        int r = idx >> 4, s = idx & 15;
        size_t src = (((size_t)(b*NSSM+h))*TT + t0 + r)*SS + s;
        hs[r][s] = g_hbuf[src];
        cs[r][s] = g_cc[src];
        ows[r][s] = Ow[(h*64 + r)*16 + s];
    }
    __syncthreads();

    const int r = tid >> 2, dp = tid & 3;
    float y = 0.f;
#pragma unroll
    for (int s = 0; s < 16; s++) y += cs[r][s]*hs[r][s];
    float x0 = g_ssmx[((size_t)(b*TT)+t0+r)*(NSSM*DD) + h*DD];
    float sc = ssm_scale[0];
    float yx = y * x0;
#pragma unroll
    for (int q = 0; q < 16; q++) {
        int d = dp*16 + q;
        float v = yx;
#pragma unroll
        for (int s = 0; s < 16; s++) v += hs[r][s]*ows[d][s];
        g_cat[((size_t)(b*TT)+t0+r)*DIMM + 512 + h*DD + d] = v*sc;
    }
}

// ---------------- launch ----------------
extern "C" void kernel_launch(void* const* d_in, const int* in_sizes, int n_in,
                              void* d_out, int out_size)
{
    const float* x         = (const float*)d_in[0];
    const float* meta      = (const float*)d_in[1];
    const float* qw        = (const float*)d_in[2];
    const float* kw        = (const float*)d_in[3];
    const float* vw        = (const float*)d_in[4];
    const float* qgain     = (const float*)d_in[5];
    const float* ssm_in_w  = (const float*)d_in[6];
    const float* projw     = (const float*)d_in[7];
    const float* attn_sc   = (const float*)d_in[8];
    const float* ssm_sc    = (const float*)d_in[9];
    const float* logA      = (const float*)d_in[10];
    const float* Bw        = (const float*)d_in[11];
    const float* Cw        = (const float*)d_in[12];
    const float* dtw       = (const float*)d_in[13];
    const float* dtb       = (const float*)d_in[14];
    const float* Ow        = (const float*)d_in[15];
    float* out = (float*)d_out;

    float *p_xext, *p_wqkv, *p_qkv, *p_cat, *p_ssmx;
    cudaGetSymbolAddress((void**)&p_xext, g_xext);
    cudaGetSymbolAddress((void**)&p_wqkv, g_wqkv);
    cudaGetSymbolAddress((void**)&p_qkv,  g_qkv);
    cudaGetSymbolAddress((void**)&p_cat,  g_cat);
    cudaGetSymbolAddress((void**)&p_ssmx, g_ssmx);

    const int ATTN_SMEM = (4*64*68 + 3*64) * (int)sizeof(float);  // 70400 B
    cudaFuncSetAttribute(attn_kernel, cudaFuncAttributeMaxDynamicSharedMemorySize, ATTN_SMEM);

    xext_kernel<<<(BB*TE*DIMM + 255)/256, 256>>>(x, meta);
    packw_kernel<<<(DIMM*DIMM + 255)/256, 256>>>(qw, kw, vw);
    gemm128_kernel<<<dim3(DIMM/128, (BB*TE + 127)/128), 256>>>(p_xext, p_wqkv, p_qkv, BB*TE, DIMM, DIMM);
    {
        int warps = BB*(NATTN+NKV)*TE;
        normrot_kernel<<<(warps*32 + 255)/256, 256>>>(qgain);
    }
    gemm128_kernel<<<dim3((NSSM*DD)/128, (BB*TT)/128), 256>>>(x, ssm_in_w, p_ssmx, BB*TT, NSSM*DD, DIMM);
    attn_kernel<<<dim3((TE + 63)/64, NATTN, BB), 128, ATTN_SMEM>>>(attn_sc);
    dtbc_kernel<<<dim3(TT/64, NSSM, BB), 256>>>(dtw, dtb, Bw, Cw, logA);
    scan_kernel<<<8, 32>>>();
    ssmout_kernel<<<dim3(TT/64, NSSM, BB), 256>>>(Ow, ssm_sc);
    gemm128_kernel<<<dim3(DIMM/128, (BB*TT)/128), 256>>>(p_cat, projw, out, BB*TT, DIMM, DIMM);
}

// round 5
// speedup vs baseline: 2.1038x; 1.9020x over previous
#include <cuda_runtime.h>
#include <cuda_bf16.h>
#include <math.h>
#include <stdint.h>

#define BB     2
#define TT     2048
#define TE     2052
#define DIMM   1024
#define DD     64
#define NATTN  8
#define NKV    4
#define NSSM   8
#define SS     16
#define NMETA  4

// ================= helpers =================
__device__ __forceinline__ uint32_t smem_u32(const void* p) {
    uint32_t a;
    asm("{ .reg .u64 t; cvta.to.shared.u64 t, %1; cvt.u32.u64 %0, t; }" : "=r"(a) : "l"(p));
    return a;
}
__device__ __forceinline__ void ldsm4(uint32_t* r, uint32_t addr) {
    asm volatile("ldmatrix.sync.aligned.m8n8.x4.shared.b16 {%0,%1,%2,%3}, [%4];"
        : "=r"(r[0]), "=r"(r[1]), "=r"(r[2]), "=r"(r[3]) : "r"(addr));
}
__device__ __forceinline__ void mma16816(float* c, const uint32_t* a, const uint32_t* b) {
    asm volatile("mma.sync.aligned.m16n8k16.row.col.f32.bf16.bf16.f32 "
        "{%0,%1,%2,%3}, {%4,%5,%6,%7}, {%8,%9}, {%0,%1,%2,%3};"
        : "+f"(c[0]), "+f"(c[1]), "+f"(c[2]), "+f"(c[3])
        : "r"(a[0]), "r"(a[1]), "r"(a[2]), "r"(a[3]), "r"(b[0]), "r"(b[1]));
}
__device__ __forceinline__ void cpasync16(uint32_t dst, const void* src, int srcsize) {
    asm volatile("cp.async.cg.shared.global [%0], [%1], 16, %2;"
        :: "r"(dst), "l"(src), "r"(srcsize) : "memory");
}

// ================= scratch =================
__device__ __nv_bfloat16 g_xh[BB*TE*DIMM];
__device__ __nv_bfloat16 g_xl[BB*TE*DIMM];
__device__ __nv_bfloat16 g_wqkvh[DIMM*DIMM];
__device__ __nv_bfloat16 g_wqkvl[DIMM*DIMM];
__device__ __nv_bfloat16 g_wsh[NSSM*DD*DIMM];
__device__ __nv_bfloat16 g_wsl[NSSM*DD*DIMM];
__device__ __nv_bfloat16 g_wph[DIMM*DIMM];
__device__ __nv_bfloat16 g_wpl[DIMM*DIMM];
__device__ __nv_bfloat16 g_cath[BB*TT*DIMM];
__device__ __nv_bfloat16 g_catl[BB*TT*DIMM];
__device__ float  g_qkv [BB*TE*DIMM];
__device__ float  g_q   [BB*NATTN*TE*DD];
__device__ float  g_k   [BB*NKV*TE*DD];
__device__ float  g_ssmx[BB*TT*NSSM*DD];
__device__ float2 g_au  [BB*NSSM*TT*SS];
__device__ float  g_cc  [BB*NSSM*TT*SS];
__device__ float  g_hbuf[BB*NSSM*TT*SS];

// ================= fused conversion: xext + all weights -> bf16 hi/lo =================
#define CV_XN (BB*TE*DIMM)
#define CV_W1 (DIMM*DIMM)
#define CV_W2 (NSSM*DD*DIMM)
#define CV_W3 (DIMM*DIMM)
__global__ void conv_all_kernel(const float* __restrict__ x, const float* __restrict__ meta,
                                const float* __restrict__ qw, const float* __restrict__ kw,
                                const float* __restrict__ vw, const float* __restrict__ sw,
                                const float* __restrict__ pw)
{
    int idx = blockIdx.x*256 + threadIdx.x;
    float v; __nv_bfloat16 *dh, *dl; int off;
    if (idx < CV_XN) {
        int c = idx & 1023, row = idx >> 10;
        int b = row / TE, t = row % TE;
        v = (t < NMETA) ? meta[t*DIMM + c] : x[((size_t)(b*TT) + (t-NMETA))*DIMM + c];
        dh = g_xh; dl = g_xl; off = idx;
    } else if (idx < CV_XN + CV_W1) {
        int j = idx - CV_XN; int r = j >> 10, c = j & 1023;
        if (r < 512)      v = qw[r*DIMM + c];
        else if (r < 768) v = kw[(r-512)*DIMM + c];
        else              v = vw[(r-768)*DIMM + c];
        dh = g_wqkvh; dl = g_wqkvl; off = j;
    } else if (idx < CV_XN + CV_W1 + CV_W2) {
        int j = idx - CV_XN - CV_W1;
        v = sw[j]; dh = g_wsh; dl = g_wsl; off = j;
    } else if (idx < CV_XN + CV_W1 + CV_W2 + CV_W3) {
        int j = idx - CV_XN - CV_W1 - CV_W2;
        v = pw[j]; dh = g_wph; dl = g_wpl; off = j;
    } else return;
    __nv_bfloat16 h = __float2bfloat16(v);
    dh[off] = h;
    dl[off] = __float2bfloat16(v - __bfloat162float(h));
}

// ================= HMMA GEMM: C[M,N] = A @ B^T, 3xBF16 compensated =================
// CTA tile 128x128, K-chunk 64 (128B swizzled rows), 8 warps (4M x 2N), warp 32x64.
__global__ void __launch_bounds__(256, 2) gemm_mma_kernel(
    const __nv_bfloat16* __restrict__ Ah, const __nv_bfloat16* __restrict__ Al,
    const __nv_bfloat16* __restrict__ Bh, const __nv_bfloat16* __restrict__ Bl,
    float* __restrict__ C, int M, int N, int remap)
{
    extern __shared__ char smc[];
    const uint32_t smb = smem_u32(smc);
    const int tid = threadIdx.x, l = tid & 31, w = tid >> 5;
    const int wm = w & 3, wn = w >> 2;
    const int m0 = blockIdx.y << 7, n0 = blockIdx.x << 7;

    float acc[2][8][4];
#pragma unroll
    for (int mi = 0; mi < 2; mi++)
#pragma unroll
        for (int nf = 0; nf < 8; nf++)
#pragma unroll
            for (int q = 0; q < 4; q++) acc[mi][nf][q] = 0.f;

    for (int c = 0; c < 16; c++) {
        // fill 4 tiles: 0=Ah 1=Al 2=Bh 3=Bl, each 128 rows x 128B (swizzled)
        for (int i = tid; i < 4096; i += 256) {
            int tile = i >> 10, idx = i & 1023, row = idx >> 3, seg = idx & 7;
            uint32_t dst = smb + tile*16384 + row*128 + ((seg*16) ^ ((row & 7) << 4));
            const __nv_bfloat16* base;
            int grow, ok = 1;
            if (tile < 2) {
                grow = m0 + row;
                ok = grow < M;
                if (!ok) grow = 0;
                else if (remap) grow += 4*((grow >> 11) + 1);
                base = (tile == 0) ? Ah : Al;
            } else {
                grow = n0 + row;
                base = (tile == 2) ? Bh : Bl;
            }
            const void* src = base + ((size_t)grow << 10) + c*64 + seg*8;
            cpasync16(dst, src, ok ? 16 : 0);
        }
        asm volatile("cp.async.commit_group;" ::: "memory");
        asm volatile("cp.async.wait_group 0;" ::: "memory");
        __syncthreads();

#pragma unroll
        for (int kk = 0; kk < 4; kk++) {
            uint32_t aH[2][4], aL[2][4], b[8][2];
            // A fragments (hi & lo)
#pragma unroll
            for (int mi = 0; mi < 2; mi++) {
                int row = wm*32 + mi*16 + (l & 15);
                int kb = kk*32 + ((l >> 4) << 4);
                uint32_t ad = smb + row*128 + (kb ^ ((row & 7) << 4));
                ldsm4(aH[mi], ad);
                ldsm4(aL[mi], ad + 16384);
            }
            // B hi fragments
#pragma unroll
            for (int nj = 0; nj < 4; nj++) {
                int row = wn*64 + nj*16 + (l & 7) + ((l >> 4) << 3);
                int kb = kk*32 + (((l >> 3) & 1) << 4);
                uint32_t bd = smb + 2*16384 + row*128 + (kb ^ ((row & 7) << 4));
                uint32_t t[4];
                ldsm4(t, bd);
                b[nj*2][0]=t[0]; b[nj*2][1]=t[1]; b[nj*2+1][0]=t[2]; b[nj*2+1][1]=t[3];
            }
            // pass 1 & 2: Ah*Bh + Al*Bh
#pragma unroll
            for (int mi = 0; mi < 2; mi++)
#pragma unroll
                for (int nf = 0; nf < 8; nf++) {
                    mma16816(acc[mi][nf], aH[mi], b[nf]);
                    mma16816(acc[mi][nf], aL[mi], b[nf]);
                }
            // B lo fragments (reuse regs)
#pragma unroll
            for (int nj = 0; nj < 4; nj++) {
                int row = wn*64 + nj*16 + (l & 7) + ((l >> 4) << 3);
                int kb = kk*32 + (((l >> 3) & 1) << 4);
                uint32_t bd = smb + 3*16384 + row*128 + (kb ^ ((row & 7) << 4));
                uint32_t t[4];
                ldsm4(t, bd);
                b[nj*2][0]=t[0]; b[nj*2][1]=t[1]; b[nj*2+1][0]=t[2]; b[nj*2+1][1]=t[3];
            }
            // pass 3: Ah*Bl
#pragma unroll
            for (int mi = 0; mi < 2; mi++)
#pragma unroll
                for (int nf = 0; nf < 8; nf++)
                    mma16816(acc[mi][nf], aH[mi], b[nf]);
        }
        __syncthreads();
    }

    // epilogue: fp32 stores
#pragma unroll
    for (int mi = 0; mi < 2; mi++) {
        int m = m0 + wm*32 + mi*16 + (l >> 2);
#pragma unroll
        for (int nf = 0; nf < 8; nf++) {
            int n = n0 + wn*64 + nf*8 + ((l & 3) << 1);
            if (m < M)
                *(float2*)&C[(size_t)m*N + n] = make_float2(acc[mi][nf][0], acc[mi][nf][1]);
            if (m + 8 < M)
                *(float2*)&C[(size_t)(m+8)*N + n] = make_float2(acc[mi][nf][2], acc[mi][nf][3]);
        }
    }
}

// ================= RMSNorm + RoPE (+q_gain) =================
__global__ void normrot_kernel(const float* __restrict__ qgain)
{
    const int QROWS = BB*NATTN*TE;
    const int KROWS = BB*NKV*TE;
    int gw = (blockIdx.x*blockDim.x + threadIdx.x) >> 5;
    int lane = threadIdx.x & 31;
    if (gw >= QROWS + KROWS) return;

    const float* src; float* dst; float gain; int t;
    if (gw < QROWS) {
        int b = gw / (NATTN*TE); int r = gw % (NATTN*TE); int h = r / TE; t = r % TE;
        src = &g_qkv[((size_t)(b*TE)+t)*DIMM + h*DD];
        dst = &g_q[(((size_t)(b*NATTN+h))*TE + t)*DD];
        gain = qgain[h];
    } else {
        int w2 = gw - QROWS;
        int b = w2 / (NKV*TE); int r = w2 % (NKV*TE); int h = r / TE; t = r % TE;
        src = &g_qkv[((size_t)(b*TE)+t)*DIMM + 512 + h*DD];
        dst = &g_k[(((size_t)(b*NKV+h))*TE + t)*DD];
        gain = 1.0f;
    }
    float x1 = src[lane], x2 = src[lane+32];
    float ss = x1*x1 + x2*x2;
#pragma unroll
    for (int o = 16; o > 0; o >>= 1) ss += __shfl_xor_sync(0xffffffffu, ss, o);
    float rinv = rsqrtf(ss*(1.0f/64.0f) + 1e-6f);
    x1 *= rinv; x2 *= rinv;
    float inv = expf(-(float)lane * 0.28782313662425575f);   // ln(10000)/32
    float f = (float)t * inv;
    float sn, cs; sincosf(f, &sn, &cs);
    dst[lane]    = (x1*cs - x2*sn) * gain;
    dst[lane+32] = (x1*sn + x2*cs) * gain;
}

// ================= causal flash attention (SIMT fp32), writes cat bf16 hi/lo =================
__global__ void __launch_bounds__(128) attn_kernel(const float* __restrict__ attn_scale)
{
    extern __shared__ float sm[];
    float* Qs  = sm;             // [64][68]
    float* Ks  = sm + 64*68;
    float* Vs  = sm + 2*64*68;
    float* Ps  = sm + 3*64*68;
    float* mrow = sm + 4*64*68;
    float* lrow = mrow + 64;
    float* arow = lrow + 64;

    const int b = blockIdx.z, h = blockIdx.y, qt = blockIdx.x;
    const int q0 = qt << 6;
    const int hkv = h >> 1;
    const int tid = threadIdx.x;
    const int tx = tid & 15, ty = tid >> 4;
    const int lr = tid >> 1;
    const int lc0 = (tid & 1) << 5;

    {
        int qrow = q0 + lr;
        const float* src = &g_q[(((size_t)(b*NATTN+h))*TE + qrow)*DD];
#pragma unroll
        for (int i = 0; i < 32; i += 4) {
            float4 v = make_float4(0,0,0,0);
            if (qrow < TE) v = *(const float4*)&src[lc0+i];
            *(float4*)&Qs[lr*68 + lc0 + i] = v;
        }
    }
    if (tid < 64) { mrow[tid] = -1e30f; lrow[tid] = 0.f; }

    float acc[8][4];
#pragma unroll
    for (int i = 0; i < 8; i++)
#pragma unroll
        for (int j = 0; j < 4; j++) acc[i][j] = 0.f;

    for (int kt = 0; kt <= qt; kt++) {
        const int k0 = kt << 6;
        __syncthreads();
        {
            int krow = k0 + lr;
            const float* ksrc = &g_k[(((size_t)(b*NKV+hkv))*TE + krow)*DD];
            const float* vsrc = &g_qkv[((size_t)(b*TE)+krow)*DIMM + 768 + hkv*DD];
#pragma unroll
            for (int i = 0; i < 32; i += 4) {
                float4 kv = make_float4(0,0,0,0), vv = make_float4(0,0,0,0);
                if (krow < TE) { kv = *(const float4*)&ksrc[lc0+i]; vv = *(const float4*)&vsrc[lc0+i]; }
                *(float4*)&Ks[lr*68 + lc0 + i] = kv;
                *(float4*)&Vs[lr*68 + lc0 + i] = vv;
            }
        }
        __syncthreads();

        float s[8][4];
#pragma unroll
        for (int i = 0; i < 8; i++)
#pragma unroll
            for (int j = 0; j < 4; j++) s[i][j] = 0.f;
#pragma unroll
        for (int kb = 0; kb < 64; kb += 4) {
            float4 k4[4];
#pragma unroll
            for (int j = 0; j < 4; j++) k4[j] = *(const float4*)&Ks[((tx<<2)+j)*68 + kb];
#pragma unroll
            for (int i = 0; i < 8; i++) {
                float4 q4 = *(const float4*)&Qs[((ty<<3)+i)*68 + kb];
                s[i][0] += q4.x*k4[0].x + q4.y*k4[0].y + q4.z*k4[0].z + q4.w*k4[0].w;
                s[i][1] += q4.x*k4[1].x + q4.y*k4[1].y + q4.z*k4[1].z + q4.w*k4[1].w;
                s[i][2] += q4.x*k4[2].x + q4.y*k4[2].y + q4.z*k4[2].z + q4.w*k4[2].w;
                s[i][3] += q4.x*k4[3].x + q4.y*k4[3].y + q4.z*k4[3].z + q4.w*k4[3].w;
            }
        }

#pragma unroll
        for (int i = 0; i < 8; i++) {
            int r = (ty<<3) + i;
            int q = q0 + r;
            float sv[4];
#pragma unroll
            for (int j = 0; j < 4; j++) {
                int kk = k0 + (tx<<2) + j;
                sv[j] = (kk <= q) ? s[i][j]*0.125f : -1e30f;
            }
            float tm = fmaxf(fmaxf(sv[0],sv[1]), fmaxf(sv[2],sv[3]));
#pragma unroll
            for (int o = 8; o > 0; o >>= 1) tm = fmaxf(tm, __shfl_xor_sync(0xffffffffu, tm, o));
            float mo = mrow[r];
            float mn = fmaxf(mo, tm);
            float p0 = __expf(sv[0]-mn), p1 = __expf(sv[1]-mn);
            float p2 = __expf(sv[2]-mn), p3 = __expf(sv[3]-mn);
            *(float4*)&Ps[r*68 + (tx<<2)] = make_float4(p0,p1,p2,p3);
            float ps = p0+p1+p2+p3;
#pragma unroll
            for (int o = 8; o > 0; o >>= 1) ps += __shfl_xor_sync(0xffffffffu, ps, o);
            if (tx == 0) {
                float al = __expf(mo - mn);
                arow[r] = al;
                lrow[r] = lrow[r]*al + ps;
                mrow[r] = mn;
            }
        }
        __syncthreads();

#pragma unroll
        for (int i = 0; i < 8; i++) {
            float al = arow[(ty<<3)+i];
            acc[i][0]*=al; acc[i][1]*=al; acc[i][2]*=al; acc[i][3]*=al;
        }
#pragma unroll
        for (int kb = 0; kb < 64; kb += 4) {
            float4 v4[4];
#pragma unroll
            for (int kk = 0; kk < 4; kk++) v4[kk] = *(const float4*)&Vs[(kb+kk)*68 + (tx<<2)];
#pragma unroll
            for (int i = 0; i < 8; i++) {
                float4 p4 = *(const float4*)&Ps[((ty<<3)+i)*68 + kb];
                acc[i][0] += p4.x*v4[0].x + p4.y*v4[1].x + p4.z*v4[2].x + p4.w*v4[3].x;
                acc[i][1] += p4.x*v4[0].y + p4.y*v4[1].y + p4.z*v4[2].y + p4.w*v4[3].y;
                acc[i][2] += p4.x*v4[0].z + p4.y*v4[1].z + p4.z*v4[2].z + p4.w*v4[3].z;
                acc[i][3] += p4.x*v4[0].w + p4.y*v4[1].w + p4.z*v4[2].w + p4.w*v4[3].w;
            }
        }
    }
    __syncthreads();
    float ascale = attn_scale[0];
#pragma unroll
    for (int i = 0; i < 8; i++) {
        int q = q0 + (ty<<3) + i;
        if (q >= NMETA && q < TE) {
            float sc = ascale / lrow[(ty<<3)+i];
            float v0 = acc[i][0]*sc, v1 = acc[i][1]*sc, v2 = acc[i][2]*sc, v3 = acc[i][3]*sc;
            size_t base = ((size_t)(b*TT) + (q-NMETA))*DIMM + h*DD + (tx<<2);
            __nv_bfloat16 h0=__float2bfloat16(v0), h1=__float2bfloat16(v1);
            __nv_bfloat16 h2=__float2bfloat16(v2), h3=__float2bfloat16(v3);
            __nv_bfloat162 ha; ha.x=h0; ha.y=h1;
            __nv_bfloat162 hb; hb.x=h2; hb.y=h3;
            *(__nv_bfloat162*)&g_cath[base]   = ha;
            *(__nv_bfloat162*)&g_cath[base+2] = hb;
            __nv_bfloat162 la, lb;
            la.x=__float2bfloat16(v0-__bfloat162float(h0));
            la.y=__float2bfloat16(v1-__bfloat162float(h1));
            lb.x=__float2bfloat16(v2-__bfloat162float(h2));
            lb.y=__float2bfloat16(v3-__bfloat162float(h3));
            *(__nv_bfloat162*)&g_catl[base]   = la;
            *(__nv_bfloat162*)&g_catl[base+2] = lb;
        }
    }
}

// ================= SSM: dt / a / Bx / Cc =================
__global__ void dtbc_kernel(const float* __restrict__ dtw, const float* __restrict__ dtb,
                            const float* __restrict__ Bw,  const float* __restrict__ Cw,
                            const float* __restrict__ logA)
{
    __shared__ float xs[64][65];
    __shared__ float ws[48][65];
    __shared__ float dts[64][16];
    const int b = blockIdx.z, h = blockIdx.y, t0 = blockIdx.x*64;
    const int tid = threadIdx.x;

    for (int idx = tid; idx < 48*64; idx += 256) {
        int o = idx >> 6, k = idx & 63;
        float v;
        if (o < 16)      v = dtw[(h*16+o)*64 + k];
        else if (o < 32) v = Bw[(h*16+(o-16))*64 + k];
        else             v = Cw[(h*16+(o-32))*64 + k];
        ws[o][k] = v;
    }
    for (int idx = tid; idx < 64*64; idx += 256) {
        int r = idx >> 6, k = idx & 63;
        xs[r][k] = g_ssmx[((size_t)(b*TT)+t0+r)*(NSSM*DD) + h*DD + k];
    }
    __syncthreads();

    const int r = tid >> 2;
    const size_t obase = (((size_t)(b*NSSM+h))*TT + t0 + r)*SS;

    {
        int so = (tid & 3) << 2;
#pragma unroll
        for (int q = 0; q < 4; q++) {
            int o = so + q;
            float d = 0.f;
#pragma unroll
            for (int k = 0; k < 64; k++) d += xs[r][k]*ws[o][k];
            d += dtb[h*16 + o];
            float sp = (d > 20.f) ? d : log1pf(expf(d));
            float dt = fminf(sp, 1.0f);
            dts[r][o] = dt;
            float A  = fminf(-expf(logA[h*16 + o]), 10.0f);
            float la = fminf(fmaxf(dt*A, -0.5f), 0.0f);
            g_au[obase + o].x = expf(la);
        }
    }
    __syncthreads();
    {
        int jo = (tid & 3) << 3;
#pragma unroll
        for (int q = 0; q < 8; q++) {
            int o2 = jo + q;
            float d = 0.f;
#pragma unroll
            for (int k = 0; k < 64; k++) d += xs[r][k]*ws[16+o2][k];
            if (o2 < 16) g_au[obase + o2].y     = d * dts[r][o2];
            else         g_cc[obase + (o2-16)]  = d;
        }
    }
}

// ================= chunk-parallel scan =================
__global__ void scan_kernel()
{
    const int bh = blockIdx.x;
    const int s = threadIdx.x & 15, ck = threadIdx.x >> 4;
    const size_t base = (size_t)bh*TT*SS;
    __shared__ float sc_c[16][17], sc_p[16][17], sc_in[16][17];

    const int t0 = ck*128;
    float hv = 0.f, p = 1.f;
    for (int t = 0; t < 128; t++) {
        float2 au = g_au[base + (size_t)(t0+t)*SS + s];
        hv = fmaf(au.x, hv, au.y);
        p *= au.x;
        g_hbuf[base + (size_t)(t0+t)*SS + s] = hv;
    }
    sc_c[ck][s] = hv; sc_p[ck][s] = p;
    __syncthreads();
    if (threadIdx.x < 16) {
        int s2 = threadIdx.x;
        float hin = 0.f;
        for (int c2 = 0; c2 < 16; c2++) {
            sc_in[c2][s2] = hin;
            hin = sc_c[c2][s2] + sc_p[c2][s2]*hin;
        }
    }
    __syncthreads();
    float hin = sc_in[ck][s];
    if (ck > 0) {
        p = 1.f;
        for (int t = 0; t < 128; t++) {
            float2 au = g_au[base + (size_t)(t0+t)*SS + s];
            p *= au.x;
            g_hbuf[base + (size_t)(t0+t)*SS + s] += p*hin;
        }
    }
}

// ================= SSM epilogue: cat[:,512:] as bf16 hi/lo =================
__global__ void ssmout_kernel(const float* __restrict__ Ow, const float* __restrict__ ssm_scale)
{
    __shared__ float hs[64][17];
    __shared__ float cs[64][17];
    __shared__ float ows[64][17];
    const int b = blockIdx.z, h = blockIdx.y, t0 = blockIdx.x*64;
    const int tid = threadIdx.x;

    for (int idx = tid; idx < 64*16; idx += 256) {
        int r = idx >> 4, s = idx & 15;
        size_t src = (((size_t)(b*NSSM+h))*TT + t0 + r)*SS + s;
        hs[r][s] = g_hbuf[src];
        cs[r][s] = g_cc[src];
        ows[r][s] = Ow[(h*64 + r)*16 + s];
    }
    __syncthreads();

    const int r = tid >> 2, dp = tid & 3;
    float y = 0.f;
#pragma unroll
    for (int s = 0; s < 16; s++) y += cs[r][s]*hs[r][s];
    float x0 = g_ssmx[((size_t)(b*TT)+t0+r)*(NSSM*DD) + h*DD];
    float sc = ssm_scale[0];
    float yx = y * x0;
    size_t ob = ((size_t)(b*TT)+t0+r)*DIMM + 512 + h*DD + dp*16;
#pragma unroll
    for (int q = 0; q < 16; q++) {
        int d = dp*16 + q;
        float v = yx;
#pragma unroll
        for (int s = 0; s < 16; s++) v += hs[r][s]*ows[d][s];
        v *= sc;
        __nv_bfloat16 hh = __float2bfloat16(v);
        g_cath[ob + q] = hh;
        g_catl[ob + q] = __float2bfloat16(v - __bfloat162float(hh));
    }
}

// ================= launch =================
extern "C" void kernel_launch(void* const* d_in, const int* in_sizes, int n_in,
                              void* d_out, int out_size)
{
    const float* x         = (const float*)d_in[0];
    const float* meta      = (const float*)d_in[1];
    const float* qw        = (const float*)d_in[2];
    const float* kw        = (const float*)d_in[3];
    const float* vw        = (const float*)d_in[4];
    const float* qgain     = (const float*)d_in[5];
    const float* ssm_in_w  = (const float*)d_in[6];
    const float* projw     = (const float*)d_in[7];
    const float* attn_sc   = (const float*)d_in[8];
    const float* ssm_sc    = (const float*)d_in[9];
    const float* logA      = (const float*)d_in[10];
    const float* Bw        = (const float*)d_in[11];
    const float* Cw        = (const float*)d_in[12];
    const float* dtw       = (const float*)d_in[13];
    const float* dtb       = (const float*)d_in[14];
    const float* Ow        = (const float*)d_in[15];
    float* out = (float*)d_out;

    __nv_bfloat16 *p_xh, *p_xl, *p_wqh, *p_wql, *p_wsh, *p_wsl, *p_wph, *p_wpl, *p_cth, *p_ctl;
    float *p_qkv, *p_ssmx;
    cudaGetSymbolAddress((void**)&p_xh,  g_xh);
    cudaGetSymbolAddress((void**)&p_xl,  g_xl);
    cudaGetSymbolAddress((void**)&p_wqh, g_wqkvh);
    cudaGetSymbolAddress((void**)&p_wql, g_wqkvl);
    cudaGetSymbolAddress((void**)&p_wsh, g_wsh);
    cudaGetSymbolAddress((void**)&p_wsl, g_wsl);
    cudaGetSymbolAddress((void**)&p_wph, g_wph);
    cudaGetSymbolAddress((void**)&p_wpl, g_wpl);
    cudaGetSymbolAddress((void**)&p_cth, g_cath);
    cudaGetSymbolAddress((void**)&p_ctl, g_catl);
    cudaGetSymbolAddress((void**)&p_qkv,  g_qkv);
    cudaGetSymbolAddress((void**)&p_ssmx, g_ssmx);

    const int GEMM_SMEM = 4*16384;                                // 65536
    cudaFuncSetAttribute(gemm_mma_kernel, cudaFuncAttributeMaxDynamicSharedMemorySize, GEMM_SMEM);
    const int ATTN_SMEM = (4*64*68 + 3*64) * (int)sizeof(float);  // 70400
    cudaFuncSetAttribute(attn_kernel, cudaFuncAttributeMaxDynamicSharedMemorySize, ATTN_SMEM);

    const int CV_TOTAL = CV_XN + CV_W1 + CV_W2 + CV_W3;

    // 1: conversions
    conv_all_kernel<<<(CV_TOTAL + 255)/256, 256>>>(x, meta, qw, kw, vw, ssm_in_w, projw);
    // 2: qkv = xext @ wqkv^T  (M=4104, N=1024)
    gemm_mma_kernel<<<dim3(DIMM/128, (BB*TE + 127)/128), 256, GEMM_SMEM>>>(
        p_xh, p_xl, p_wqh, p_wql, p_qkv, BB*TE, DIMM, 0);
    // 3: rmsnorm + rope
    {
        int warps = BB*(NATTN+NKV)*TE;
        normrot_kernel<<<(warps*32 + 255)/256, 256>>>(qgain);
    }
    // 4: attention
    attn_kernel<<<dim3((TE + 63)/64, NATTN, BB), 128, ATTN_SMEM>>>(attn_sc);
    // 5: ssmx = x @ ssm_in_w^T  (M=4096 via row-remap of xext, N=512)
    gemm_mma_kernel<<<dim3((NSSM*DD)/128, (BB*TT)/128), 256, GEMM_SMEM>>>(
        p_xh, p_xl, p_wsh, p_wsl, p_ssmx, BB*TT, NSSM*DD, 1);
    // 6-8: ssm
    dtbc_kernel<<<dim3(TT/64, NSSM, BB), 256>>>(dtw, dtb, Bw, Cw, logA);
    scan_kernel<<<BB*NSSM, 256>>>();
    ssmout_kernel<<<dim3(TT/64, NSSM, BB), 256>>>(Ow, ssm_sc);
    // 9: out = cat @ proj^T
    gemm_mma_kernel<<<dim3(DIMM/128, (BB*TT)/128), 256, GEMM_SMEM>>>(
        p_cth, p_ctl, p_wph, p_wpl, out, BB*TT, DIMM, 0);
}

// round 7
// speedup vs baseline: 3.9391x; 1.8723x over previous
#include <cuda_runtime.h>
#include <cuda_bf16.h>
#include <math.h>
#include <stdint.h>

#define BB     2
#define TT     2048
#define TE     2052
#define DIMM   1024
#define DD     64
#define NATTN  8
#define NKV    4
#define NSSM   8
#define SS     16
#define NMETA  4

// ================= helpers =================
__device__ __forceinline__ uint32_t smem_u32(const void* p) {
    uint32_t a;
    asm("{ .reg .u64 t; cvta.to.shared.u64 t, %1; cvt.u32.u64 %0, t; }" : "=r"(a) : "l"(p));
    return a;
}
__device__ __forceinline__ void ldsm4(uint32_t* r, uint32_t addr) {
    asm volatile("ldmatrix.sync.aligned.m8n8.x4.shared.b16 {%0,%1,%2,%3}, [%4];"
        : "=r"(r[0]), "=r"(r[1]), "=r"(r[2]), "=r"(r[3]) : "r"(addr));
}
__device__ __forceinline__ void ldsm4t(uint32_t* r, uint32_t addr) {
    asm volatile("ldmatrix.sync.aligned.m8n8.x4.trans.shared.b16 {%0,%1,%2,%3}, [%4];"
        : "=r"(r[0]), "=r"(r[1]), "=r"(r[2]), "=r"(r[3]) : "r"(addr));
}
__device__ __forceinline__ void mma16816(float* c, const uint32_t* a, const uint32_t* b) {
    asm volatile("mma.sync.aligned.m16n8k16.row.col.f32.bf16.bf16.f32 "
        "{%0,%1,%2,%3}, {%4,%5,%6,%7}, {%8,%9}, {%0,%1,%2,%3};"
        : "+f"(c[0]), "+f"(c[1]), "+f"(c[2]), "+f"(c[3])
        : "r"(a[0]), "r"(a[1]), "r"(a[2]), "r"(a[3]), "r"(b[0]), "r"(b[1]));
}
__device__ __forceinline__ void cpasync16(uint32_t dst, const void* src, int srcsize) {
    asm volatile("cp.async.cg.shared.global [%0], [%1], 16, %2;"
        :: "r"(dst), "l"(src), "r"(srcsize) : "memory");
}
__device__ __forceinline__ void bfsplit2(float x, float y, uint32_t& hi, uint32_t& lo) {
    __nv_bfloat162 h2, l2;
    h2.x = __float2bfloat16(x); h2.y = __float2bfloat16(y);
    l2.x = __float2bfloat16(x - __bfloat162float(h2.x));
    l2.y = __float2bfloat16(y - __bfloat162float(h2.y));
    hi = *(uint32_t*)&h2; lo = *(uint32_t*)&l2;
}

// ================= scratch =================
__device__ __nv_bfloat16 g_xh[BB*TE*DIMM];
__device__ __nv_bfloat16 g_xl[BB*TE*DIMM];
__device__ __nv_bfloat16 g_wqkvh[DIMM*DIMM];
__device__ __nv_bfloat16 g_wqkvl[DIMM*DIMM];
__device__ __nv_bfloat16 g_wsh[NSSM*DD*DIMM];
__device__ __nv_bfloat16 g_wsl[NSSM*DD*DIMM];
__device__ __nv_bfloat16 g_wph[DIMM*DIMM];
__device__ __nv_bfloat16 g_wpl[DIMM*DIMM];
__device__ __nv_bfloat16 g_cath[BB*TT*DIMM];
__device__ __nv_bfloat16 g_catl[BB*TT*DIMM];
__device__ __nv_bfloat16 g_qh[BB*NATTN*TE*DD];
__device__ __nv_bfloat16 g_ql[BB*NATTN*TE*DD];
__device__ __nv_bfloat16 g_kh[BB*NKV*TE*DD];
__device__ __nv_bfloat16 g_kl[BB*NKV*TE*DD];
__device__ __nv_bfloat16 g_vh[BB*NKV*TE*DD];
__device__ __nv_bfloat16 g_vl[BB*NKV*TE*DD];
__device__ float  g_qkv [BB*TE*DIMM];
__device__ float  g_ssmx[BB*TT*NSSM*DD];
__device__ float2 g_au  [BB*NSSM*TT*SS];
__device__ float  g_cc  [BB*NSSM*TT*SS];
__device__ float  g_hbuf[BB*NSSM*TT*SS];

// ================= fused conversion: xext + all weights -> bf16 hi/lo =================
#define CV_XN (BB*TE*DIMM)
#define CV_W1 (DIMM*DIMM)
#define CV_W2 (NSSM*DD*DIMM)
#define CV_W3 (DIMM*DIMM)
__global__ void conv_all_kernel(const float* __restrict__ x, const float* __restrict__ meta,
                                const float* __restrict__ qw, const float* __restrict__ kw,
                                const float* __restrict__ vw, const float* __restrict__ sw,
                                const float* __restrict__ pw)
{
    int idx = blockIdx.x*256 + threadIdx.x;
    float v; __nv_bfloat16 *dh, *dl; int off;
    if (idx < CV_XN) {
        int c = idx & 1023, row = idx >> 10;
        int b = row / TE, t = row % TE;
        v = (t < NMETA) ? meta[t*DIMM + c] : x[((size_t)(b*TT) + (t-NMETA))*DIMM + c];
        dh = g_xh; dl = g_xl; off = idx;
    } else if (idx < CV_XN + CV_W1) {
        int j = idx - CV_XN; int r = j >> 10, c = j & 1023;
        if (r < 512)      v = qw[r*DIMM + c];
        else if (r < 768) v = kw[(r-512)*DIMM + c];
        else              v = vw[(r-768)*DIMM + c];
        dh = g_wqkvh; dl = g_wqkvl; off = j;
    } else if (idx < CV_XN + CV_W1 + CV_W2) {
        int j = idx - CV_XN - CV_W1;
        v = sw[j]; dh = g_wsh; dl = g_wsl; off = j;
    } else if (idx < CV_XN + CV_W1 + CV_W2 + CV_W3) {
        int j = idx - CV_XN - CV_W1 - CV_W2;
        v = pw[j]; dh = g_wph; dl = g_wpl; off = j;
    } else return;
    __nv_bfloat16 h = __float2bfloat16(v);
    dh[off] = h;
    dl[off] = __float2bfloat16(v - __bfloat162float(h));
}

// ================= HMMA GEMM: C[M,N] = A @ B^T, 3xBF16 compensated =================
__global__ void __launch_bounds__(256, 2) gemm_mma_kernel(
    const __nv_bfloat16* __restrict__ Ah, const __nv_bfloat16* __restrict__ Al,
    const __nv_bfloat16* __restrict__ Bh, const __nv_bfloat16* __restrict__ Bl,
    float* __restrict__ C, int M, int N, int remap)
{
    extern __shared__ char smc[];
    const uint32_t smb = smem_u32(smc);
    const int tid = threadIdx.x, l = tid & 31, w = tid >> 5;
    const int wm = w & 3, wn = w >> 2;
    const int m0 = blockIdx.y << 7, n0 = blockIdx.x << 7;

    float acc[2][8][4];
#pragma unroll
    for (int mi = 0; mi < 2; mi++)
#pragma unroll
        for (int nf = 0; nf < 8; nf++)
#pragma unroll
            for (int q = 0; q < 4; q++) acc[mi][nf][q] = 0.f;

    for (int c = 0; c < 16; c++) {
        for (int i = tid; i < 4096; i += 256) {
            int tile = i >> 10, idx = i & 1023, row = idx >> 3, seg = idx & 7;
            uint32_t dst = smb + tile*16384 + row*128 + ((seg*16) ^ ((row & 7) << 4));
            const __nv_bfloat16* base;
            int grow, ok = 1;
            if (tile < 2) {
                grow = m0 + row;
                ok = grow < M;
                if (!ok) grow = 0;
                else if (remap) grow += 4*((grow >> 11) + 1);
                base = (tile == 0) ? Ah : Al;
            } else {
                grow = n0 + row;
                base = (tile == 2) ? Bh : Bl;
            }
            const void* src = base + ((size_t)grow << 10) + c*64 + seg*8;
            cpasync16(dst, src, ok ? 16 : 0);
        }
        asm volatile("cp.async.commit_group;" ::: "memory");
        asm volatile("cp.async.wait_group 0;" ::: "memory");
        __syncthreads();

#pragma unroll
        for (int kk = 0; kk < 4; kk++) {
            uint32_t aH[2][4], aL[2][4], b[8][2];
#pragma unroll
            for (int mi = 0; mi < 2; mi++) {
                int row = wm*32 + mi*16 + (l & 15);
                int kb = kk*32 + ((l >> 4) << 4);
                uint32_t ad = smb + row*128 + (kb ^ ((row & 7) << 4));
                ldsm4(aH[mi], ad);
                ldsm4(aL[mi], ad + 16384);
            }
#pragma unroll
            for (int nj = 0; nj < 4; nj++) {
                int row = wn*64 + nj*16 + (l & 7) + ((l >> 4) << 3);
                int kb = kk*32 + (((l >> 3) & 1) << 4);
                uint32_t bd = smb + 2*16384 + row*128 + (kb ^ ((row & 7) << 4));
                uint32_t t[4];
                ldsm4(t, bd);
                b[nj*2][0]=t[0]; b[nj*2][1]=t[1]; b[nj*2+1][0]=t[2]; b[nj*2+1][1]=t[3];
            }
#pragma unroll
            for (int mi = 0; mi < 2; mi++)
#pragma unroll
                for (int nf = 0; nf < 8; nf++) {
                    mma16816(acc[mi][nf], aH[mi], b[nf]);
                    mma16816(acc[mi][nf], aL[mi], b[nf]);
                }
#pragma unroll
            for (int nj = 0; nj < 4; nj++) {
                int row = wn*64 + nj*16 + (l & 7) + ((l >> 4) << 3);
                int kb = kk*32 + (((l >> 3) & 1) << 4);
                uint32_t bd = smb + 3*16384 + row*128 + (kb ^ ((row & 7) << 4));
                uint32_t t[4];
                ldsm4(t, bd);
                b[nj*2][0]=t[0]; b[nj*2][1]=t[1]; b[nj*2+1][0]=t[2]; b[nj*2+1][1]=t[3];
            }
#pragma unroll
            for (int mi = 0; mi < 2; mi++)
#pragma unroll
                for (int nf = 0; nf < 8; nf++)
                    mma16816(acc[mi][nf], aH[mi], b[nf]);
        }
        __syncthreads();
    }

#pragma unroll
    for (int mi = 0; mi < 2; mi++) {
        int m = m0 + wm*32 + mi*16 + (l >> 2);
#pragma unroll
        for (int nf = 0; nf < 8; nf++) {
            int n = n0 + wn*64 + nf*8 + ((l & 3) << 1);
            if (m < M)
                *(float2*)&C[(size_t)m*N + n] = make_float2(acc[mi][nf][0], acc[mi][nf][1]);
            if (m + 8 < M)
                *(float2*)&C[(size_t)(m+8)*N + n] = make_float2(acc[mi][nf][2], acc[mi][nf][3]);
        }
    }
}

// ================= RMSNorm + RoPE (+q_gain) -> bf16 hi/lo; V convert =================
__global__ void normrot_kernel(const float* __restrict__ qgain)
{
    const int QROWS = BB*NATTN*TE;
    const int KROWS = BB*NKV*TE;
    const int VROWS = BB*NKV*TE;
    int gw = (blockIdx.x*blockDim.x + threadIdx.x) >> 5;
    int lane = threadIdx.x & 31;
    if (gw >= QROWS + KROWS + VROWS) return;

    if (gw < QROWS + KROWS) {
        const float* src; __nv_bfloat16 *dh, *dl; size_t doff; float gain; int t;
        if (gw < QROWS) {
            int b = gw / (NATTN*TE); int r = gw % (NATTN*TE); int h = r / TE; t = r % TE;
            src = &g_qkv[((size_t)(b*TE)+t)*DIMM + h*DD];
            doff = (((size_t)(b*NATTN+h))*TE + t)*DD;
            dh = g_qh; dl = g_ql;
            gain = qgain[h];
        } else {
            int w2 = gw - QROWS;
            int b = w2 / (NKV*TE); int r = w2 % (NKV*TE); int h = r / TE; t = r % TE;
            src = &g_qkv[((size_t)(b*TE)+t)*DIMM + 512 + h*DD];
            doff = (((size_t)(b*NKV+h))*TE + t)*DD;
            dh = g_kh; dl = g_kl;
            gain = 1.0f;
        }
        float x1 = src[lane], x2 = src[lane+32];
        float ss = x1*x1 + x2*x2;
#pragma unroll
        for (int o = 16; o > 0; o >>= 1) ss += __shfl_xor_sync(0xffffffffu, ss, o);
        float rinv = rsqrtf(ss*(1.0f/64.0f) + 1e-6f);
        x1 *= rinv; x2 *= rinv;
        float inv = expf(-(float)lane * 0.28782313662425575f);   // ln(10000)/32
        float f = (float)t * inv;
        float sn, cs; sincosf(f, &sn, &cs);
        float y1 = (x1*cs - x2*sn) * gain;
        float y2 = (x1*sn + x2*cs) * gain;
        __nv_bfloat16 h1 = __float2bfloat16(y1), h2 = __float2bfloat16(y2);
        dh[doff + lane]      = h1;
        dh[doff + lane + 32] = h2;
        dl[doff + lane]      = __float2bfloat16(y1 - __bfloat162float(h1));
        dl[doff + lane + 32] = __float2bfloat16(y2 - __bfloat162float(h2));
    } else {
        int w2 = gw - QROWS - KROWS;
        int b = w2 / (NKV*TE); int r = w2 % (NKV*TE); int h = r / TE; int t = r % TE;
        const float* src = &g_qkv[((size_t)(b*TE)+t)*DIMM + 768 + h*DD];
        size_t doff = (((size_t)(b*NKV+h))*TE + t)*DD;
        float v1 = src[lane], v2 = src[lane+32];
        __nv_bfloat16 h1 = __float2bfloat16(v1), h2 = __float2bfloat16(v2);
        g_vh[doff + lane]      = h1;
        g_vh[doff + lane + 32] = h2;
        g_vl[doff + lane]      = __float2bfloat16(v1 - __bfloat162float(h1));
        g_vl[doff + lane + 32] = __float2bfloat16(v2 - __bfloat162float(h2));
    }
}

// ================= HMMA flash attention, 3xBF16 compensated =================
// Block: one (b, h, 64-row q-tile). 4 warps x 16 q-rows. smem: Qh Ql | Kh Kl Vh Vl (8KB each).
__global__ void __launch_bounds__(128) attn_mma_kernel(const float* __restrict__ attn_scale)
{
    extern __shared__ char smc[];
    const uint32_t smb = smem_u32(smc);
    const int b = blockIdx.z, h = blockIdx.y;
    const int qt = (int)(gridDim.x - 1 - blockIdx.x);     // heavy tiles first
    const int q0 = qt << 6;
    const int hkv = h >> 1;
    const int tid = threadIdx.x, l = tid & 31, w = tid >> 5;

    // Q tiles hi/lo
    {
        const size_t qbase = ((size_t)(b*NATTN+h))*TE;
        for (int i = tid; i < 1024; i += 128) {
            int tile = i >> 9, idx = i & 511, row = idx >> 3, seg = idx & 7;
            uint32_t dst = smb + tile*8192 + row*128 + ((seg*16) ^ ((row & 7) << 4));
            int qrow = q0 + row;
            int ok = qrow < TE;
            const __nv_bfloat16* base = tile ? g_ql : g_qh;
            const void* src = base + (qbase + (ok ? qrow : 0))*DD + seg*8;
            cpasync16(dst, src, ok ? 16 : 0);
        }
        asm volatile("cp.async.commit_group;" ::: "memory");
    }

    float sO[8][4];
#pragma unroll
    for (int nf = 0; nf < 8; nf++)
#pragma unroll
        for (int q = 0; q < 4; q++) sO[nf][q] = 0.f;
    float m0r = -1e30f, m1r = -1e30f, l0r = 0.f, l1r = 0.f;

    const size_t kvbase = ((size_t)(b*NKV+hkv))*TE;
    const int grow0 = q0 + w*16 + (l >> 2);
    const int grow1 = grow0 + 8;

    for (int kt = 0; kt <= qt; kt++) {
        const int k0 = kt << 6;
        if (kt) __syncthreads();   // previous K/V fully consumed
        // K,V hi/lo tiles
        for (int i = tid; i < 2048; i += 128) {
            int tile = i >> 9, idx = i & 511, row = idx >> 3, seg = idx & 7;
            uint32_t dst = smb + 16384 + tile*8192 + row*128 + ((seg*16) ^ ((row & 7) << 4));
            int krow = k0 + row;
            int ok = krow < TE;
            const __nv_bfloat16* base = (tile == 0) ? g_kh : (tile == 1) ? g_kl
                                      : (tile == 2) ? g_vh : g_vl;
            const void* src = base + (kvbase + (ok ? krow : 0))*DD + seg*8;
            cpasync16(dst, src, ok ? 16 : 0);
        }
        asm volatile("cp.async.commit_group;" ::: "memory");
        asm volatile("cp.async.wait_group 0;" ::: "memory");
        __syncthreads();

        // ---- S = Q K^T (3-pass compensated) ----
        float s[8][4];
#pragma unroll
        for (int nf = 0; nf < 8; nf++)
#pragma unroll
            for (int q = 0; q < 4; q++) s[nf][q] = 0.f;

#pragma unroll
        for (int kc = 0; kc < 4; kc++) {
            uint32_t aH[4], aL[4], bk[8][2];
            {
                int row = w*16 + (l & 15);
                int kb = kc*32 + ((l >> 4) << 4);
                uint32_t ad = smb + row*128 + (kb ^ ((row & 7) << 4));
                ldsm4(aH, ad);
                ldsm4(aL, ad + 8192);
            }
#pragma unroll
            for (int nj = 0; nj < 4; nj++) {
                int row = nj*16 + (l & 7) + ((l >> 4) << 3);
                int kb = kc*32 + (((l >> 3) & 1) << 4);
                uint32_t bd = smb + 16384 + row*128 + (kb ^ ((row & 7) << 4));
                uint32_t t[4];
                ldsm4(t, bd);
                bk[nj*2][0]=t[0]; bk[nj*2][1]=t[1]; bk[nj*2+1][0]=t[2]; bk[nj*2+1][1]=t[3];
            }
#pragma unroll
            for (int nf = 0; nf < 8; nf++) {
                mma16816(s[nf], aH, bk[nf]);
                mma16816(s[nf], aL, bk[nf]);
            }
#pragma unroll
            for (int nj = 0; nj < 4; nj++) {
                int row = nj*16 + (l & 7) + ((l >> 4) << 3);
                int kb = kc*32 + (((l >> 3) & 1) << 4);
                uint32_t bd = smb + 24576 + row*128 + (kb ^ ((row & 7) << 4));
                uint32_t t[4];
                ldsm4(t, bd);
                bk[nj*2][0]=t[0]; bk[nj*2][1]=t[1]; bk[nj*2+1][0]=t[2]; bk[nj*2+1][1]=t[3];
            }
#pragma unroll
            for (int nf = 0; nf < 8; nf++)
                mma16816(s[nf], aH, bk[nf]);
        }

        // ---- scale + mask ----
        const bool diag = (kt == qt);
#pragma unroll
        for (int nf = 0; nf < 8; nf++) {
            int c0 = k0 + nf*8 + ((l & 3) << 1);
            s[nf][0] *= 0.125f; s[nf][1] *= 0.125f;
            s[nf][2] *= 0.125f; s[nf][3] *= 0.125f;
            if (diag) {
                if (c0     > grow0) s[nf][0] = -1e30f;
                if (c0 + 1 > grow0) s[nf][1] = -1e30f;
                if (c0     > grow1) s[nf][2] = -1e30f;
                if (c0 + 1 > grow1) s[nf][3] = -1e30f;
            }
        }

        // ---- online softmax ----
        float mx0 = -1e30f, mx1 = -1e30f;
#pragma unroll
        for (int nf = 0; nf < 8; nf++) {
            mx0 = fmaxf(mx0, fmaxf(s[nf][0], s[nf][1]));
            mx1 = fmaxf(mx1, fmaxf(s[nf][2], s[nf][3]));
        }
        mx0 = fmaxf(mx0, __shfl_xor_sync(0xffffffffu, mx0, 1));
        mx0 = fmaxf(mx0, __shfl_xor_sync(0xffffffffu, mx0, 2));
        mx1 = fmaxf(mx1, __shfl_xor_sync(0xffffffffu, mx1, 1));
        mx1 = fmaxf(mx1, __shfl_xor_sync(0xffffffffu, mx1, 2));
        float mn0 = fmaxf(m0r, mx0), mn1 = fmaxf(m1r, mx1);
        float al0 = __expf(m0r - mn0), al1 = __expf(m1r - mn1);
        m0r = mn0; m1r = mn1;

        float rs0 = 0.f, rs1 = 0.f;
#pragma unroll
        for (int nf = 0; nf < 8; nf++) {
            float p0 = __expf(s[nf][0] - mn0), p1 = __expf(s[nf][1] - mn0);
            float p2 = __expf(s[nf][2] - mn1), p3 = __expf(s[nf][3] - mn1);
            rs0 += p0 + p1; rs1 += p2 + p3;
            s[nf][0] = p0; s[nf][1] = p1; s[nf][2] = p2; s[nf][3] = p3;
        }
        rs0 += __shfl_xor_sync(0xffffffffu, rs0, 1);
        rs0 += __shfl_xor_sync(0xffffffffu, rs0, 2);
        rs1 += __shfl_xor_sync(0xffffffffu, rs1, 1);
        rs1 += __shfl_xor_sync(0xffffffffu, rs1, 2);
        l0r = l0r*al0 + rs0;
        l1r = l1r*al1 + rs1;

#pragma unroll
        for (int nf = 0; nf < 8; nf++) {
            sO[nf][0] *= al0; sO[nf][1] *= al0;
            sO[nf][2] *= al1; sO[nf][3] *= al1;
        }

        // ---- O += P V (3-pass compensated) ----
#pragma unroll
        for (int kc = 0; kc < 4; kc++) {
            uint32_t pH[4], pL[4], bv[8][2];
            bfsplit2(s[2*kc][0],   s[2*kc][1],   pH[0], pL[0]);
            bfsplit2(s[2*kc][2],   s[2*kc][3],   pH[1], pL[1]);
            bfsplit2(s[2*kc+1][0], s[2*kc+1][1], pH[2], pL[2]);
            bfsplit2(s[2*kc+1][2], s[2*kc+1][3], pH[3], pL[3]);
#pragma unroll
            for (int i2 = 0; i2 < 4; i2++) {
                int row = kc*16 + (l & 7) + (((l >> 3) & 1) << 3);
                int cb = i2*32 + (((l >> 4) & 1) << 4);
                uint32_t vd = smb + 32768 + row*128 + (cb ^ ((row & 7) << 4));
                uint32_t t[4];
                ldsm4t(t, vd);
                bv[2*i2][0]=t[0]; bv[2*i2][1]=t[1]; bv[2*i2+1][0]=t[2]; bv[2*i2+1][1]=t[3];
            }
#pragma unroll
            for (int nf = 0; nf < 8; nf++) {
                mma16816(sO[nf], pH, bv[nf]);
                mma16816(sO[nf], pL, bv[nf]);
            }
#pragma unroll
            for (int i2 = 0; i2 < 4; i2++) {
                int row = kc*16 + (l & 7) + (((l >> 3) & 1) << 3);
                int cb = i2*32 + (((l >> 4) & 1) << 4);
                uint32_t vd = smb + 40960 + row*128 + (cb ^ ((row & 7) << 4));
                uint32_t t[4];
                ldsm4t(t, vd);
                bv[2*i2][0]=t[0]; bv[2*i2][1]=t[1]; bv[2*i2+1][0]=t[2]; bv[2*i2+1][1]=t[3];
            }
#pragma unroll
            for (int nf = 0; nf < 8; nf++)
                mma16816(sO[nf], pH, bv[nf]);
        }
    }

    // ---- epilogue ----
    float ascale = attn_scale[0];
    float inv0 = ascale / l0r, inv1 = ascale / l1r;
#pragma unroll
    for (int nf = 0; nf < 8; nf++) {
        int oc = h*DD + nf*8 + ((l & 3) << 1);
        if (grow0 >= NMETA && grow0 < TE) {
            float v0 = sO[nf][0]*inv0, v1 = sO[nf][1]*inv0;
            uint32_t hi, lo; bfsplit2(v0, v1, hi, lo);
            size_t base = ((size_t)(b*TT) + (grow0 - NMETA))*DIMM + oc;
            *(uint32_t*)&g_cath[base] = hi;
            *(uint32_t*)&g_catl[base] = lo;
        }
        if (grow1 >= NMETA && grow1 < TE) {
            float v2 = sO[nf][2]*inv1, v3 = sO[nf][3]*inv1;
            uint32_t hi, lo; bfsplit2(v2, v3, hi, lo);
            size_t base = ((size_t)(b*TT) + (grow1 - NMETA))*DIMM + oc;
            *(uint32_t*)&g_cath[base] = hi;
            *(uint32_t*)&g_catl[base] = lo;
        }
    }
}

// ================= SSM: dt / a / Bx / Cc =================
__global__ void dtbc_kernel(const float* __restrict__ dtw, const float* __restrict__ dtb,
                            const float* __restrict__ Bw,  const float* __restrict__ Cw,
                            const float* __restrict__ logA)
{
    __shared__ float xs[64][65];
    __shared__ float ws[48][65];
    __shared__ float dts[64][16];
    const int b = blockIdx.z, h = blockIdx.y, t0 = blockIdx.x*64;
    const int tid = threadIdx.x;

    for (int idx = tid; idx < 48*64; idx += 256) {
        int o = idx >> 6, k = idx & 63;
        float v;
        if (o < 16)      v = dtw[(h*16+o)*64 + k];
        else if (o < 32) v = Bw[(h*16+(o-16))*64 + k];
        else             v = Cw[(h*16+(o-32))*64 + k];
        ws[o][k] = v;
    }
    for (int idx = tid; idx < 64*64; idx += 256) {
        int r = idx >> 6, k = idx & 63;
        xs[r][k] = g_ssmx[((size_t)(b*TT)+t0+r)*(NSSM*DD) + h*DD + k];
    }
    __syncthreads();

    const int r = tid >> 2;
    const size_t obase = (((size_t)(b*NSSM+h))*TT + t0 + r)*SS;

    {
        int so = (tid & 3) << 2;
#pragma unroll
        for (int q = 0; q < 4; q++) {
            int o = so + q;
            float d = 0.f;
#pragma unroll
            for (int k = 0; k < 64; k++) d += xs[r][k]*ws[o][k];
            d += dtb[h*16 + o];
            float sp = (d > 20.f) ? d : log1pf(expf(d));
            float dt = fminf(sp, 1.0f);
            dts[r][o] = dt;
            float A  = fminf(-expf(logA[h*16 + o]), 10.0f);
            float la = fminf(fmaxf(dt*A, -0.5f), 0.0f);
            g_au[obase + o].x = expf(la);
        }
    }
    __syncthreads();
    {
        int jo = (tid & 3) << 3;
#pragma unroll
        for (int q = 0; q < 8; q++) {
            int o2 = jo + q;
            float d = 0.f;
#pragma unroll
            for (int k = 0; k < 64; k++) d += xs[r][k]*ws[16+o2][k];
            if (o2 < 16) g_au[obase + o2].y     = d * dts[r][o2];
            else         g_cc[obase + (o2-16)]  = d;
        }
    }
}

// ================= chunk-parallel scan =================
__global__ void scan_kernel()
{
    const int bh = blockIdx.x;
    const int s = threadIdx.x & 15, ck = threadIdx.x >> 4;
    const size_t base = (size_t)bh*TT*SS;
    __shared__ float sc_c[16][17], sc_p[16][17], sc_in[16][17];

    const int t0 = ck*128;
    float hv = 0.f, p = 1.f;
    for (int t = 0; t < 128; t++) {
        float2 au = g_au[base + (size_t)(t0+t)*SS + s];
        hv = fmaf(au.x, hv, au.y);
        p *= au.x;
        g_hbuf[base + (size_t)(t0+t)*SS + s] = hv;
    }
    sc_c[ck][s] = hv; sc_p[ck][s] = p;
    __syncthreads();
    if (threadIdx.x < 16) {
        int s2 = threadIdx.x;
        float hin = 0.f;
        for (int c2 = 0; c2 < 16; c2++) {
            sc_in[c2][s2] = hin;
            hin = sc_c[c2][s2] + sc_p[c2][s2]*hin;
        }
    }
    __syncthreads();
    float hin = sc_in[ck][s];
    if (ck > 0) {
        p = 1.f;
        for (int t = 0; t < 128; t++) {
            float2 au = g_au[base + (size_t)(t0+t)*SS + s];
            p *= au.x;
            g_hbuf[base + (size_t)(t0+t)*SS + s] += p*hin;
        }
    }
}

// ================= SSM epilogue: cat[:,512:] as bf16 hi/lo =================
__global__ void ssmout_kernel(const float* __restrict__ Ow, const float* __restrict__ ssm_scale)
{
    __shared__ float hs[64][17];
    __shared__ float cs[64][17];
    __shared__ float ows[64][17];
    const int b = blockIdx.z, h = blockIdx.y, t0 = blockIdx.x*64;
    const int tid = threadIdx.x;

    for (int idx = tid; idx < 64*16; idx += 256) {
        int r = idx >> 4, s = idx & 15;
        size_t src = (((size_t)(b*NSSM+h))*TT + t0 + r)*SS + s;
        hs[r][s] = g_hbuf[src];
        cs[r][s] = g_cc[src];
        ows[r][s] = Ow[(h*64 + r)*16 + s];
    }
    __syncthreads();

    const int r = tid >> 2, dp = tid & 3;
    float y = 0.f;
#pragma unroll
    for (int s = 0; s < 16; s++) y += cs[r][s]*hs[r][s];
    float x0 = g_ssmx[((size_t)(b*TT)+t0+r)*(NSSM*DD) + h*DD];
    float sc = ssm_scale[0];
    float yx = y * x0;
    size_t ob = ((size_t)(b*TT)+t0+r)*DIMM + 512 + h*DD + dp*16;
#pragma unroll
    for (int q = 0; q < 16; q++) {
        int d = dp*16 + q;
        float v = yx;
#pragma unroll
        for (int s = 0; s < 16; s++) v += hs[r][s]*ows[d][s];
        v *= sc;
        __nv_bfloat16 hh = __float2bfloat16(v);
        g_cath[ob + q] = hh;
        g_catl[ob + q] = __float2bfloat16(v - __bfloat162float(hh));
    }
}

// ================= launch =================
extern "C" void kernel_launch(void* const* d_in, const int* in_sizes, int n_in,
                              void* d_out, int out_size)
{
    const float* x         = (const float*)d_in[0];
    const float* meta      = (const float*)d_in[1];
    const float* qw        = (const float*)d_in[2];
    const float* kw        = (const float*)d_in[3];
    const float* vw        = (const float*)d_in[4];
    const float* qgain     = (const float*)d_in[5];
    const float* ssm_in_w  = (const float*)d_in[6];
    const float* projw     = (const float*)d_in[7];
    const float* attn_sc   = (const float*)d_in[8];
    const float* ssm_sc    = (const float*)d_in[9];
    const float* logA      = (const float*)d_in[10];
    const float* Bw        = (const float*)d_in[11];
    const float* Cw        = (const float*)d_in[12];
    const float* dtw       = (const float*)d_in[13];
    const float* dtb       = (const float*)d_in[14];
    const float* Ow        = (const float*)d_in[15];
    float* out = (float*)d_out;

    __nv_bfloat16 *p_xh, *p_xl, *p_wqh, *p_wql, *p_wsh, *p_wsl, *p_wph, *p_wpl, *p_cth, *p_ctl;
    float *p_qkv, *p_ssmx;
    cudaGetSymbolAddress((void**)&p_xh,  g_xh);
    cudaGetSymbolAddress((void**)&p_xl,  g_xl);
    cudaGetSymbolAddress((void**)&p_wqh, g_wqkvh);
    cudaGetSymbolAddress((void**)&p_wql, g_wqkvl);
    cudaGetSymbolAddress((void**)&p_wsh, g_wsh);
    cudaGetSymbolAddress((void**)&p_wsl, g_wsl);
    cudaGetSymbolAddress((void**)&p_wph, g_wph);
    cudaGetSymbolAddress((void**)&p_wpl, g_wpl);
    cudaGetSymbolAddress((void**)&p_cth, g_cath);
    cudaGetSymbolAddress((void**)&p_ctl, g_catl);
    cudaGetSymbolAddress((void**)&p_qkv,  g_qkv);
    cudaGetSymbolAddress((void**)&p_ssmx, g_ssmx);

    const int GEMM_SMEM = 4*16384;
    cudaFuncSetAttribute(gemm_mma_kernel, cudaFuncAttributeMaxDynamicSharedMemorySize, GEMM_SMEM);
    const int ATTN_SMEM = 6*8192;                                 // 49152
    cudaFuncSetAttribute(attn_mma_kernel, cudaFuncAttributeMaxDynamicSharedMemorySize, ATTN_SMEM);

    const int CV_TOTAL = CV_XN + CV_W1 + CV_W2 + CV_W3;

    // 1: conversions
    conv_all_kernel<<<(CV_TOTAL + 255)/256, 256>>>(x, meta, qw, kw, vw, ssm_in_w, projw);
    // 2: qkv = xext @ wqkv^T
    gemm_mma_kernel<<<dim3(DIMM/128, (BB*TE + 127)/128), 256, GEMM_SMEM>>>(
        p_xh, p_xl, p_wqh, p_wql, p_qkv, BB*TE, DIMM, 0);
    // 3: rmsnorm + rope + v-convert
    {
        int warps = BB*(NATTN + NKV + NKV)*TE;
        normrot_kernel<<<(warps*32 + 255)/256, 256>>>(qgain);
    }
    // 4: attention (HMMA)
    attn_mma_kernel<<<dim3((TE + 63)/64, NATTN, BB), 128, ATTN_SMEM>>>(attn_sc);
    // 5: ssmx = x @ ssm_in_w^T
    gemm_mma_kernel<<<dim3((NSSM*DD)/128, (BB*TT)/128), 256, GEMM_SMEM>>>(
        p_xh, p_xl, p_wsh, p_wsl, p_ssmx, BB*TT, NSSM*DD, 1);
    // 6-8: ssm
    dtbc_kernel<<<dim3(TT/64, NSSM, BB), 256>>>(dtw, dtb, Bw, Cw, logA);
    scan_kernel<<<BB*NSSM, 256>>>();
    ssmout_kernel<<<dim3(TT/64, NSSM, BB), 256>>>(Ow, ssm_sc);
    // 9: out = cat @ proj^T
    gemm_mma_kernel<<<dim3(DIMM/128, (BB*TT)/128), 256, GEMM_SMEM>>>(
        p_cth, p_ctl, p_wph, p_wpl, out, BB*TT, DIMM, 0);
}

// round 8
// speedup vs baseline: 4.0873x; 1.0376x over previous
#include <cuda_runtime.h>
#include <cuda_bf16.h>
#include <math.h>
#include <stdint.h>

#define BB     2
#define TT     2048
#define TE     2052
#define DIMM   1024
#define DD     64
#define NATTN  8
#define NKV    4
#define NSSM   8
#define SS     16
#define NMETA  4

// ================= helpers =================
__device__ __forceinline__ uint32_t smem_u32(const void* p) {
    uint32_t a;
    asm("{ .reg .u64 t; cvta.to.shared.u64 t, %1; cvt.u32.u64 %0, t; }" : "=r"(a) : "l"(p));
    return a;
}
__device__ __forceinline__ void ldsm4(uint32_t* r, uint32_t addr) {
    asm volatile("ldmatrix.sync.aligned.m8n8.x4.shared.b16 {%0,%1,%2,%3}, [%4];"
        : "=r"(r[0]), "=r"(r[1]), "=r"(r[2]), "=r"(r[3]) : "r"(addr));
}
__device__ __forceinline__ void ldsm4t(uint32_t* r, uint32_t addr) {
    asm volatile("ldmatrix.sync.aligned.m8n8.x4.trans.shared.b16 {%0,%1,%2,%3}, [%4];"
        : "=r"(r[0]), "=r"(r[1]), "=r"(r[2]), "=r"(r[3]) : "r"(addr));
}
__device__ __forceinline__ void mma16816(float* c, const uint32_t* a, const uint32_t* b) {
    asm volatile("mma.sync.aligned.m16n8k16.row.col.f32.bf16.bf16.f32 "
        "{%0,%1,%2,%3}, {%4,%5,%6,%7}, {%8,%9}, {%0,%1,%2,%3};"
        : "+f"(c[0]), "+f"(c[1]), "+f"(c[2]), "+f"(c[3])
        : "r"(a[0]), "r"(a[1]), "r"(a[2]), "r"(a[3]), "r"(b[0]), "r"(b[1]));
}
__device__ __forceinline__ void cpasync16(uint32_t dst, const void* src, int srcsize) {
    asm volatile("cp.async.cg.shared.global [%0], [%1], 16, %2;"
        :: "r"(dst), "l"(src), "r"(srcsize) : "memory");
}
#define CP_COMMIT() asm volatile("cp.async.commit_group;" ::: "memory")
#define CP_WAIT0()  asm volatile("cp.async.wait_group 0;" ::: "memory")
#define CP_WAIT1()  asm volatile("cp.async.wait_group 1;" ::: "memory")
__device__ __forceinline__ void bfsplit2(float x, float y, uint32_t& hi, uint32_t& lo) {
    __nv_bfloat162 h2, l2;
    h2.x = __float2bfloat16(x); h2.y = __float2bfloat16(y);
    l2.x = __float2bfloat16(x - __bfloat162float(h2.x));
    l2.y = __float2bfloat16(y - __bfloat162float(h2.y));
    hi = *(uint32_t*)&h2; lo = *(uint32_t*)&l2;
}

// ================= scratch =================
__device__ __nv_bfloat16 g_xh[BB*TE*DIMM];
__device__ __nv_bfloat16 g_xl[BB*TE*DIMM];
__device__ __nv_bfloat16 g_wqkvh[DIMM*DIMM];
__device__ __nv_bfloat16 g_wqkvl[DIMM*DIMM];
__device__ __nv_bfloat16 g_wsh[NSSM*DD*DIMM];
__device__ __nv_bfloat16 g_wsl[NSSM*DD*DIMM];
__device__ __nv_bfloat16 g_wph[DIMM*DIMM];
__device__ __nv_bfloat16 g_wpl[DIMM*DIMM];
__device__ __nv_bfloat16 g_cath[BB*TT*DIMM];
__device__ __nv_bfloat16 g_catl[BB*TT*DIMM];
__device__ __nv_bfloat16 g_qh[BB*NATTN*TE*DD];
__device__ __nv_bfloat16 g_ql[BB*NATTN*TE*DD];
__device__ __nv_bfloat16 g_kh[BB*NKV*TE*DD];
__device__ __nv_bfloat16 g_kl[BB*NKV*TE*DD];
__device__ __nv_bfloat16 g_vh[BB*NKV*TE*DD];
__device__ __nv_bfloat16 g_vl[BB*NKV*TE*DD];
__device__ float  g_qkv [BB*TE*DIMM];
__device__ float  g_ssmx[BB*TT*NSSM*DD];
__device__ float2 g_au  [BB*NSSM*TT*SS];
__device__ float  g_cc  [BB*NSSM*TT*SS];
__device__ float  g_hbuf[BB*NSSM*TT*SS];

// ================= fused conversion =================
#define CV_XN (BB*TE*DIMM)
#define CV_W1 (DIMM*DIMM)
#define CV_W2 (NSSM*DD*DIMM)
#define CV_W3 (DIMM*DIMM)
__global__ void conv_all_kernel(const float* __restrict__ x, const float* __restrict__ meta,
                                const float* __restrict__ qw, const float* __restrict__ kw,
                                const float* __restrict__ vw, const float* __restrict__ sw,
                                const float* __restrict__ pw)
{
    int idx = blockIdx.x*256 + threadIdx.x;
    float v; __nv_bfloat16 *dh, *dl; int off;
    if (idx < CV_XN) {
        int c = idx & 1023, row = idx >> 10;
        int b = row / TE, t = row % TE;
        v = (t < NMETA) ? meta[t*DIMM + c] : x[((size_t)(b*TT) + (t-NMETA))*DIMM + c];
        dh = g_xh; dl = g_xl; off = idx;
    } else if (idx < CV_XN + CV_W1) {
        int j = idx - CV_XN; int r = j >> 10, c = j & 1023;
        if (r < 512)      v = qw[r*DIMM + c];
        else if (r < 768) v = kw[(r-512)*DIMM + c];
        else              v = vw[(r-768)*DIMM + c];
        dh = g_wqkvh; dl = g_wqkvl; off = j;
    } else if (idx < CV_XN + CV_W1 + CV_W2) {
        int j = idx - CV_XN - CV_W1;
        v = sw[j]; dh = g_wsh; dl = g_wsl; off = j;
    } else if (idx < CV_XN + CV_W1 + CV_W2 + CV_W3) {
        int j = idx - CV_XN - CV_W1 - CV_W2;
        v = pw[j]; dh = g_wph; dl = g_wpl; off = j;
    } else return;
    __nv_bfloat16 h = __float2bfloat16(v);
    dh[off] = h;
    dl[off] = __float2bfloat16(v - __bfloat162float(h));
}

// ================= HMMA GEMM, 3xBF16 compensated, 2-stage pipelined =================
// K-chunk 32. smem row = 128B = [32k hi | 32k lo]. Stage: A tile 16KB + B tile 16KB.
// Stage stride 32KB; total 64KB.
__global__ void __launch_bounds__(256, 2) gemm_mma_kernel(
    const __nv_bfloat16* __restrict__ Ah, const __nv_bfloat16* __restrict__ Al,
    const __nv_bfloat16* __restrict__ Bh, const __nv_bfloat16* __restrict__ Bl,
    float* __restrict__ C, int M, int N, int remap)
{
    extern __shared__ char smc[];
    const uint32_t smb = smem_u32(smc);
    const int tid = threadIdx.x, l = tid & 31, w = tid >> 5;
    const int wm = w & 3, wn = w >> 2;
    const int m0 = blockIdx.y << 7, n0 = blockIdx.x << 7;

    float acc[2][8][4];
#pragma unroll
    for (int mi = 0; mi < 2; mi++)
#pragma unroll
        for (int nf = 0; nf < 8; nf++)
#pragma unroll
            for (int q = 0; q < 4; q++) acc[mi][nf][q] = 0.f;

    // fill stage st with chunk c (32 k-elems): 2048 16B units
    auto fill = [&](int st, int c) {
        for (int i = tid; i < 2048; i += 256) {
            int tile = i >> 10, idx = i & 1023, row = idx >> 3, seg = idx & 7;
            uint32_t dst = smb + st*32768 + tile*16384 + row*128 + ((seg*16) ^ ((row & 7) << 4));
            const __nv_bfloat16* base;
            int grow, ok = 1;
            if (tile == 0) {
                grow = m0 + row;
                ok = grow < M;
                if (!ok) grow = 0;
                else if (remap) grow += 4*((grow >> 11) + 1);
                base = (seg < 4) ? Ah : Al;
            } else {
                grow = n0 + row;
                base = (seg < 4) ? Bh : Bl;
            }
            const void* src = base + ((size_t)grow << 10) + c*32 + (seg & 3)*8;
            cpasync16(dst, src, ok ? 16 : 0);
        }
        CP_COMMIT();
    };

    fill(0, 0);
    for (int c = 0; c < 32; c++) {
        const int st = c & 1;
        CP_WAIT0();
        __syncthreads();
        if (c + 1 < 32) fill(st ^ 1, c + 1);

        const uint32_t sA = smb + st*32768;
        const uint32_t sB = sA + 16384;
#pragma unroll
        for (int kk = 0; kk < 2; kk++) {
            uint32_t aH[2][4], aL[2][4], b[8][2];
#pragma unroll
            for (int mi = 0; mi < 2; mi++) {
                int row = wm*32 + mi*16 + (l & 15);
                int kb = kk*32 + ((l >> 4) << 4);
                uint32_t sw = (uint32_t)((row & 7) << 4);
                ldsm4(aH[mi], sA + row*128 + (kb ^ sw));
                ldsm4(aL[mi], sA + row*128 + ((kb + 64) ^ sw));
            }
#pragma unroll
            for (int nj = 0; nj < 4; nj++) {
                int row = wn*64 + nj*16 + (l & 7) + ((l >> 4) << 3);
                int kb = kk*32 + (((l >> 3) & 1) << 4);
                uint32_t t[4];
                ldsm4(t, sB + row*128 + (kb ^ ((row & 7) << 4)));
                b[nj*2][0]=t[0]; b[nj*2][1]=t[1]; b[nj*2+1][0]=t[2]; b[nj*2+1][1]=t[3];
            }
#pragma unroll
            for (int mi = 0; mi < 2; mi++)
#pragma unroll
                for (int nf = 0; nf < 8; nf++) {
                    mma16816(acc[mi][nf], aH[mi], b[nf]);
                    mma16816(acc[mi][nf], aL[mi], b[nf]);
                }
#pragma unroll
            for (int nj = 0; nj < 4; nj++) {
                int row = wn*64 + nj*16 + (l & 7) + ((l >> 4) << 3);
                int kb = kk*32 + (((l >> 3) & 1) << 4);
                uint32_t t[4];
                ldsm4(t, sB + row*128 + ((kb + 64) ^ ((row & 7) << 4)));
                b[nj*2][0]=t[0]; b[nj*2][1]=t[1]; b[nj*2+1][0]=t[2]; b[nj*2+1][1]=t[3];
            }
#pragma unroll
            for (int mi = 0; mi < 2; mi++)
#pragma unroll
                for (int nf = 0; nf < 8; nf++)
                    mma16816(acc[mi][nf], aH[mi], b[nf]);
        }
        __syncthreads();
    }

#pragma unroll
    for (int mi = 0; mi < 2; mi++) {
        int m = m0 + wm*32 + mi*16 + (l >> 2);
#pragma unroll
        for (int nf = 0; nf < 8; nf++) {
            int n = n0 + wn*64 + nf*8 + ((l & 3) << 1);
            if (m < M)
                *(float2*)&C[(size_t)m*N + n] = make_float2(acc[mi][nf][0], acc[mi][nf][1]);
            if (m + 8 < M)
                *(float2*)&C[(size_t)(m+8)*N + n] = make_float2(acc[mi][nf][2], acc[mi][nf][3]);
        }
    }
}

// ================= RMSNorm + RoPE (+q_gain) -> bf16 hi/lo; V convert =================
__global__ void normrot_kernel(const float* __restrict__ qgain)
{
    const int QROWS = BB*NATTN*TE;
    const int KROWS = BB*NKV*TE;
    const int VROWS = BB*NKV*TE;
    int gw = (blockIdx.x*blockDim.x + threadIdx.x) >> 5;
    int lane = threadIdx.x & 31;
    if (gw >= QROWS + KROWS + VROWS) return;

    if (gw < QROWS + KROWS) {
        const float* src; __nv_bfloat16 *dh, *dl; size_t doff; float gain; int t;
        if (gw < QROWS) {
            int b = gw / (NATTN*TE); int r = gw % (NATTN*TE); int h = r / TE; t = r % TE;
            src = &g_qkv[((size_t)(b*TE)+t)*DIMM + h*DD];
            doff = (((size_t)(b*NATTN+h))*TE + t)*DD;
            dh = g_qh; dl = g_ql;
            gain = qgain[h];
        } else {
            int w2 = gw - QROWS;
            int b = w2 / (NKV*TE); int r = w2 % (NKV*TE); int h = r / TE; t = r % TE;
            src = &g_qkv[((size_t)(b*TE)+t)*DIMM + 512 + h*DD];
            doff = (((size_t)(b*NKV+h))*TE + t)*DD;
            dh = g_kh; dl = g_kl;
            gain = 1.0f;
        }
        float x1 = src[lane], x2 = src[lane+32];
        float ss = x1*x1 + x2*x2;
#pragma unroll
        for (int o = 16; o > 0; o >>= 1) ss += __shfl_xor_sync(0xffffffffu, ss, o);
        float rinv = rsqrtf(ss*(1.0f/64.0f) + 1e-6f);
        x1 *= rinv; x2 *= rinv;
        float inv = expf(-(float)lane * 0.28782313662425575f);
        float f = (float)t * inv;
        float sn, cs; sincosf(f, &sn, &cs);
        float y1 = (x1*cs - x2*sn) * gain;
        float y2 = (x1*sn + x2*cs) * gain;
        __nv_bfloat16 h1 = __float2bfloat16(y1), h2 = __float2bfloat16(y2);
        dh[doff + lane]      = h1;
        dh[doff + lane + 32] = h2;
        dl[doff + lane]      = __float2bfloat16(y1 - __bfloat162float(h1));
        dl[doff + lane + 32] = __float2bfloat16(y2 - __bfloat162float(h2));
    } else {
        int w2 = gw - QROWS - KROWS;
        int b = w2 / (NKV*TE); int r = w2 % (NKV*TE); int h = r / TE; int t = r % TE;
        const float* src = &g_qkv[((size_t)(b*TE)+t)*DIMM + 768 + h*DD];
        size_t doff = (((size_t)(b*NKV+h))*TE + t)*DD;
        float v1 = src[lane], v2 = src[lane+32];
        __nv_bfloat16 h1 = __float2bfloat16(v1), h2 = __float2bfloat16(v2);
        g_vh[doff + lane]      = h1;
        g_vh[doff + lane + 32] = h2;
        g_vl[doff + lane]      = __float2bfloat16(v1 - __bfloat162float(h1));
        g_vl[doff + lane + 32] = __float2bfloat16(v2 - __bfloat162float(h2));
    }
}

// ================= HMMA flash attention, pipelined K/V loads =================
// smem: Qh 0 | Ql 8K | Kh 16K | Kl 24K | Vh 32K | Vl 40K  (48KB)
__global__ void __launch_bounds__(128) attn_mma_kernel(const float* __restrict__ attn_scale)
{
    extern __shared__ char smc[];
    const uint32_t smb = smem_u32(smc);
    const int b = blockIdx.z, h = blockIdx.y;
    const int qt = (int)(gridDim.x - 1 - blockIdx.x);
    const int q0 = qt << 6;
    const int hkv = h >> 1;
    const int tid = threadIdx.x, l = tid & 31, w = tid >> 5;

    const size_t qbase = ((size_t)(b*NATTN+h))*TE;
    const size_t kvbase = ((size_t)(b*NKV+hkv))*TE;

    auto loadK = [&](int k0) {
        for (int i = tid; i < 1024; i += 128) {
            int tile = i >> 9, idx = i & 511, row = idx >> 3, seg = idx & 7;
            uint32_t dst = smb + 16384 + tile*8192 + row*128 + ((seg*16) ^ ((row & 7) << 4));
            int krow = k0 + row;
            int ok = krow < TE;
            const __nv_bfloat16* base = tile ? g_kl : g_kh;
            cpasync16(dst, base + (kvbase + (ok ? krow : 0))*DD + seg*8, ok ? 16 : 0);
        }
        CP_COMMIT();
    };
    auto loadV = [&](int k0) {
        for (int i = tid; i < 1024; i += 128) {
            int tile = i >> 9, idx = i & 511, row = idx >> 3, seg = idx & 7;
            uint32_t dst = smb + 32768 + tile*8192 + row*128 + ((seg*16) ^ ((row & 7) << 4));
            int krow = k0 + row;
            int ok = krow < TE;
            const __nv_bfloat16* base = tile ? g_vl : g_vh;
            cpasync16(dst, base + (kvbase + (ok ? krow : 0))*DD + seg*8, ok ? 16 : 0);
        }
        CP_COMMIT();
    };

    // prologue: {Q, K0} group, {V0} group
    {
        for (int i = tid; i < 1024; i += 128) {
            int tile = i >> 9, idx = i & 511, row = idx >> 3, seg = idx & 7;
            uint32_t dst = smb + tile*8192 + row*128 + ((seg*16) ^ ((row & 7) << 4));
            int qrow = q0 + row;
            int ok = qrow < TE;
            const __nv_bfloat16* base = tile ? g_ql : g_qh;
            cpasync16(dst, base + (qbase + (ok ? qrow : 0))*DD + seg*8, ok ? 16 : 0);
        }
        for (int i = tid; i < 1024; i += 128) {
            int tile = i >> 9, idx = i & 511, row = idx >> 3, seg = idx & 7;
            uint32_t dst = smb + 16384 + tile*8192 + row*128 + ((seg*16) ^ ((row & 7) << 4));
            int krow = row;
            const __nv_bfloat16* base = tile ? g_kl : g_kh;
            cpasync16(dst, base + (kvbase + krow)*DD + seg*8, 16);
        }
        CP_COMMIT();
        loadV(0);
    }

    float sO[8][4];
#pragma unroll
    for (int nf = 0; nf < 8; nf++)
#pragma unroll
        for (int q = 0; q < 4; q++) sO[nf][q] = 0.f;
    float m0r = -1e30f, m1r = -1e30f, l0r = 0.f, l1r = 0.f;

    const int grow0 = q0 + w*16 + (l >> 2);
    const int grow1 = grow0 + 8;

    for (int kt = 0; kt <= qt; kt++) {
        const int k0 = kt << 6;
        CP_WAIT1();            // K(kt) (and Q) ready; V(kt) may be in flight
        __syncthreads();

        // ---- S = Q K^T ----
        float s[8][4];
#pragma unroll
        for (int nf = 0; nf < 8; nf++)
#pragma unroll
            for (int q = 0; q < 4; q++) s[nf][q] = 0.f;

#pragma unroll
        for (int kc = 0; kc < 4; kc++) {
            uint32_t aH[4], aL[4], bk[8][2];
            {
                int row = w*16 + (l & 15);
                int kb = kc*32 + ((l >> 4) << 4);
                uint32_t ad = smb + row*128 + (kb ^ ((row & 7) << 4));
                ldsm4(aH, ad);
                ldsm4(aL, ad + 8192);
            }
#pragma unroll
            for (int nj = 0; nj < 4; nj++) {
                int row = nj*16 + (l & 7) + ((l >> 4) << 3);
                int kb = kc*32 + (((l >> 3) & 1) << 4);
                uint32_t bd = smb + 16384 + row*128 + (kb ^ ((row & 7) << 4));
                uint32_t t[4];
                ldsm4(t, bd);
                bk[nj*2][0]=t[0]; bk[nj*2][1]=t[1]; bk[nj*2+1][0]=t[2]; bk[nj*2+1][1]=t[3];
            }
#pragma unroll
            for (int nf = 0; nf < 8; nf++) {
                mma16816(s[nf], aH, bk[nf]);
                mma16816(s[nf], aL, bk[nf]);
            }
#pragma unroll
            for (int nj = 0; nj < 4; nj++) {
                int row = nj*16 + (l & 7) + ((l >> 4) << 3);
                int kb = kc*32 + (((l >> 3) & 1) << 4);
                uint32_t bd = smb + 24576 + row*128 + (kb ^ ((row & 7) << 4));
                uint32_t t[4];
                ldsm4(t, bd);
                bk[nj*2][0]=t[0]; bk[nj*2][1]=t[1]; bk[nj*2+1][0]=t[2]; bk[nj*2+1][1]=t[3];
            }
#pragma unroll
            for (int nf = 0; nf < 8; nf++)
                mma16816(s[nf], aH, bk[nf]);
        }
        __syncthreads();               // K buffer consumed by all warps
        if (kt < qt) loadK(k0 + 64);   // prefetch next K under softmax+PV

        // ---- scale + mask ----
        const bool diag = (kt == qt);
#pragma unroll
        for (int nf = 0; nf < 8; nf++) {
            int c0 = k0 + nf*8 + ((l & 3) << 1);
            s[nf][0] *= 0.125f; s[nf][1] *= 0.125f;
            s[nf][2] *= 0.125f; s[nf][3] *= 0.125f;
            if (diag) {
                if (c0     > grow0) s[nf][0] = -1e30f;
                if (c0 + 1 > grow0) s[nf][1] = -1e30f;
                if (c0     > grow1) s[nf][2] = -1e30f;
                if (c0 + 1 > grow1) s[nf][3] = -1e30f;
            }
        }

        // ---- online softmax ----
        float mx0 = -1e30f, mx1 = -1e30f;
#pragma unroll
        for (int nf = 0; nf < 8; nf++) {
            mx0 = fmaxf(mx0, fmaxf(s[nf][0], s[nf][1]));
            mx1 = fmaxf(mx1, fmaxf(s[nf][2], s[nf][3]));
        }
        mx0 = fmaxf(mx0, __shfl_xor_sync(0xffffffffu, mx0, 1));
        mx0 = fmaxf(mx0, __shfl_xor_sync(0xffffffffu, mx0, 2));
        mx1 = fmaxf(mx1, __shfl_xor_sync(0xffffffffu, mx1, 1));
        mx1 = fmaxf(mx1, __shfl_xor_sync(0xffffffffu, mx1, 2));
        float mn0 = fmaxf(m0r, mx0), mn1 = fmaxf(m1r, mx1);
        float al0 = __expf(m0r - mn0), al1 = __expf(m1r - mn1);
        m0r = mn0; m1r = mn1;

        float rs0 = 0.f, rs1 = 0.f;
#pragma unroll
        for (int nf = 0; nf < 8; nf++) {
            float p0 = __expf(s[nf][0] - mn0), p1 = __expf(s[nf][1] - mn0);
            float p2 = __expf(s[nf][2] - mn1), p3 = __expf(s[nf][3] - mn1);
            rs0 += p0 + p1; rs1 += p2 + p3;
            s[nf][0] = p0; s[nf][1] = p1; s[nf][2] = p2; s[nf][3] = p3;
        }
        rs0 += __shfl_xor_sync(0xffffffffu, rs0, 1);
        rs0 += __shfl_xor_sync(0xffffffffu, rs0, 2);
        rs1 += __shfl_xor_sync(0xffffffffu, rs1, 1);
        rs1 += __shfl_xor_sync(0xffffffffu, rs1, 2);
        l0r = l0r*al0 + rs0;
        l1r = l1r*al1 + rs1;

#pragma unroll
        for (int nf = 0; nf < 8; nf++) {
            sO[nf][0] *= al0; sO[nf][1] *= al0;
            sO[nf][2] *= al1; sO[nf][3] *= al1;
        }

        // ---- wait V(kt) ----
        if (kt < qt) { CP_WAIT1(); } else { CP_WAIT0(); }
        __syncthreads();

        // ---- O += P V ----
#pragma unroll
        for (int kc = 0; kc < 4; kc++) {
            uint32_t pH[4], pL[4], bv[8][2];
            bfsplit2(s[2*kc][0],   s[2*kc][1],   pH[0], pL[0]);
            bfsplit2(s[2*kc][2],   s[2*kc][3],   pH[1], pL[1]);
            bfsplit2(s[2*kc+1][0], s[2*kc+1][1], pH[2], pL[2]);
            bfsplit2(s[2*kc+1][2], s[2*kc+1][3], pH[3], pL[3]);
#pragma unroll
            for (int i2 = 0; i2 < 4; i2++) {
                int row = kc*16 + (l & 7) + (((l >> 3) & 1) << 3);
                int cb = i2*32 + (((l >> 4) & 1) << 4);
                uint32_t vd = smb + 32768 + row*128 + (cb ^ ((row & 7) << 4));
                uint32_t t[4];
                ldsm4t(t, vd);
                bv[2*i2][0]=t[0]; bv[2*i2][1]=t[1]; bv[2*i2+1][0]=t[2]; bv[2*i2+1][1]=t[3];
            }
#pragma unroll
            for (int nf = 0; nf < 8; nf++) {
                mma16816(sO[nf], pH, bv[nf]);
                mma16816(sO[nf], pL, bv[nf]);
            }
#pragma unroll
            for (int i2 = 0; i2 < 4; i2++) {
                int row = kc*16 + (l & 7) + (((l >> 3) & 1) << 3);
                int cb = i2*32 + (((l >> 4) & 1) << 4);
                uint32_t vd = smb + 40960 + row*128 + (cb ^ ((row & 7) << 4));
                uint32_t t[4];
                ldsm4t(t, vd);
                bv[2*i2][0]=t[0]; bv[2*i2][1]=t[1]; bv[2*i2+1][0]=t[2]; bv[2*i2+1][1]=t[3];
            }
#pragma unroll
            for (int nf = 0; nf < 8; nf++)
                mma16816(sO[nf], pH, bv[nf]);
        }
        __syncthreads();               // V consumed
        if (kt < qt) loadV(k0 + 64);   // prefetch next V under next S
    }

    // ---- epilogue ----
    float ascale = attn_scale[0];
    float inv0 = ascale / l0r, inv1 = ascale / l1r;
#pragma unroll
    for (int nf = 0; nf < 8; nf++) {
        int oc = h*DD + nf*8 + ((l & 3) << 1);
        if (grow0 >= NMETA && grow0 < TE) {
            float v0 = sO[nf][0]*inv0, v1 = sO[nf][1]*inv0;
            uint32_t hi, lo; bfsplit2(v0, v1, hi, lo);
            size_t base = ((size_t)(b*TT) + (grow0 - NMETA))*DIMM + oc;
            *(uint32_t*)&g_cath[base] = hi;
            *(uint32_t*)&g_catl[base] = lo;
        }
        if (grow1 >= NMETA && grow1 < TE) {
            float v2 = sO[nf][2]*inv1, v3 = sO[nf][3]*inv1;
            uint32_t hi, lo; bfsplit2(v2, v3, hi, lo);
            size_t base = ((size_t)(b*TT) + (grow1 - NMETA))*DIMM + oc;
            *(uint32_t*)&g_cath[base] = hi;
            *(uint32_t*)&g_catl[base] = lo;
        }
    }
}

// ================= SSM: dt / a / Bx / Cc =================
__global__ void dtbc_kernel(const float* __restrict__ dtw, const float* __restrict__ dtb,
                            const float* __restrict__ Bw,  const float* __restrict__ Cw,
                            const float* __restrict__ logA)
{
    __shared__ float xs[64][65];
    __shared__ float ws[48][65];
    __shared__ float dts[64][16];
    const int b = blockIdx.z, h = blockIdx.y, t0 = blockIdx.x*64;
    const int tid = threadIdx.x;

    for (int idx = tid; idx < 48*64; idx += 256) {
        int o = idx >> 6, k = idx & 63;
        float v;
        if (o < 16)      v = dtw[(h*16+o)*64 + k];
        else if (o < 32) v = Bw[(h*16+(o-16))*64 + k];
        else             v = Cw[(h*16+(o-32))*64 + k];
        ws[o][k] = v;
    }
    for (int idx = tid; idx < 64*64; idx += 256) {
        int r = idx >> 6, k = idx & 63;
        xs[r][k] = g_ssmx[((size_t)(b*TT)+t0+r)*(NSSM*DD) + h*DD + k];
    }
    __syncthreads();

    const int r = tid >> 2;
    const size_t obase = (((size_t)(b*NSSM+h))*TT + t0 + r)*SS;

    {
        int so = (tid & 3) << 2;
#pragma unroll
        for (int q = 0; q < 4; q++) {
            int o = so + q;
            float d = 0.f;
#pragma unroll
            for (int k = 0; k < 64; k++) d += xs[r][k]*ws[o][k];
            d += dtb[h*16 + o];
            float sp = (d > 20.f) ? d : log1pf(expf(d));
            float dt = fminf(sp, 1.0f);
            dts[r][o] = dt;
            float A  = fminf(-expf(logA[h*16 + o]), 10.0f);
            float la = fminf(fmaxf(dt*A, -0.5f), 0.0f);
            g_au[obase + o].x = expf(la);
        }
    }
    __syncthreads();
    {
        int jo = (tid & 3) << 3;
#pragma unroll
        for (int q = 0; q < 8; q++) {
            int o2 = jo + q;
            float d = 0.f;
#pragma unroll
            for (int k = 0; k < 64; k++) d += xs[r][k]*ws[16+o2][k];
            if (o2 < 16) g_au[obase + o2].y     = d * dts[r][o2];
            else         g_cc[obase + (o2-16)]  = d;
        }
    }
}

// ================= chunk-parallel scan =================
__global__ void scan_kernel()
{
    const int bh = blockIdx.x;
    const int s = threadIdx.x & 15, ck = threadIdx.x >> 4;
    const size_t base = (size_t)bh*TT*SS;
    __shared__ float sc_c[16][17], sc_p[16][17], sc_in[16][17];

    const int t0 = ck*128;
    float hv = 0.f, p = 1.f;
    for (int t = 0; t < 128; t++) {
        float2 au = g_au[base + (size_t)(t0+t)*SS + s];
        hv = fmaf(au.x, hv, au.y);
        p *= au.x;
        g_hbuf[base + (size_t)(t0+t)*SS + s] = hv;
    }
    sc_c[ck][s] = hv; sc_p[ck][s] = p;
    __syncthreads();
    if (threadIdx.x < 16) {
        int s2 = threadIdx.x;
        float hin = 0.f;
        for (int c2 = 0; c2 < 16; c2++) {
            sc_in[c2][s2] = hin;
            hin = sc_c[c2][s2] + sc_p[c2][s2]*hin;
        }
    }
    __syncthreads();
    float hin = sc_in[ck][s];
    if (ck > 0) {
        p = 1.f;
        for (int t = 0; t < 128; t++) {
            float2 au = g_au[base + (size_t)(t0+t)*SS + s];
            p *= au.x;
            g_hbuf[base + (size_t)(t0+t)*SS + s] += p*hin;
        }
    }
}

// ================= SSM epilogue =================
__global__ void ssmout_kernel(const float* __restrict__ Ow, const float* __restrict__ ssm_scale)
{
    __shared__ float hs[64][17];
    __shared__ float cs[64][17];
    __shared__ float ows[64][17];
    const int b = blockIdx.z, h = blockIdx.y, t0 = blockIdx.x*64;
    const int tid = threadIdx.x;

    for (int idx = tid; idx < 64*16; idx += 256) {
        int r = idx >> 4, s = idx & 15;
        size_t src = (((size_t)(b*NSSM+h))*TT + t0 + r)*SS + s;
        hs[r][s] = g_hbuf[src];
        cs[r][s] = g_cc[src];
        ows[r][s] = Ow[(h*64 + r)*16 + s];
    }
    __syncthreads();

    const int r = tid >> 2, dp = tid & 3;
    float y = 0.f;
#pragma unroll
    for (int s = 0; s < 16; s++) y += cs[r][s]*hs[r][s];
    float x0 = g_ssmx[((size_t)(b*TT)+t0+r)*(NSSM*DD) + h*DD];
    float sc = ssm_scale[0];
    float yx = y * x0;
    size_t ob = ((size_t)(b*TT)+t0+r)*DIMM + 512 + h*DD + dp*16;
#pragma unroll
    for (int q = 0; q < 16; q++) {
        int d = dp*16 + q;
        float v = yx;
#pragma unroll
        for (int s = 0; s < 16; s++) v += hs[r][s]*ows[d][s];
        v *= sc;
        __nv_bfloat16 hh = __float2bfloat16(v);
        g_cath[ob + q] = hh;
        g_catl[ob + q] = __float2bfloat16(v - __bfloat162float(hh));
    }
}

// ================= launch =================
extern "C" void kernel_launch(void* const* d_in, const int* in_sizes, int n_in,
                              void* d_out, int out_size)
{
    const float* x         = (const float*)d_in[0];
    const float* meta      = (const float*)d_in[1];
    const float* qw        = (const float*)d_in[2];
    const float* kw        = (const float*)d_in[3];
    const float* vw        = (const float*)d_in[4];
    const float* qgain     = (const float*)d_in[5];
    const float* ssm_in_w  = (const float*)d_in[6];
    const float* projw     = (const float*)d_in[7];
    const float* attn_sc   = (const float*)d_in[8];
    const float* ssm_sc    = (const float*)d_in[9];
    const float* logA      = (const float*)d_in[10];
    const float* Bw        = (const float*)d_in[11];
    const float* Cw        = (const float*)d_in[12];
    const float* dtw       = (const float*)d_in[13];
    const float* dtb       = (const float*)d_in[14];
    const float* Ow        = (const float*)d_in[15];
    float* out = (float*)d_out;

    __nv_bfloat16 *p_xh, *p_xl, *p_wqh, *p_wql, *p_wsh, *p_wsl, *p_wph, *p_wpl, *p_cth, *p_ctl;
    float *p_qkv, *p_ssmx;
    cudaGetSymbolAddress((void**)&p_xh,  g_xh);
    cudaGetSymbolAddress((void**)&p_xl,  g_xl);
    cudaGetSymbolAddress((void**)&p_wqh, g_wqkvh);
    cudaGetSymbolAddress((void**)&p_wql, g_wqkvl);
    cudaGetSymbolAddress((void**)&p_wsh, g_wsh);
    cudaGetSymbolAddress((void**)&p_wsl, g_wsl);
    cudaGetSymbolAddress((void**)&p_wph, g_wph);
    cudaGetSymbolAddress((void**)&p_wpl, g_wpl);
    cudaGetSymbolAddress((void**)&p_cth, g_cath);
    cudaGetSymbolAddress((void**)&p_ctl, g_catl);
    cudaGetSymbolAddress((void**)&p_qkv,  g_qkv);
    cudaGetSymbolAddress((void**)&p_ssmx, g_ssmx);

    const int GEMM_SMEM = 2*32768;                                // 65536
    cudaFuncSetAttribute(gemm_mma_kernel, cudaFuncAttributeMaxDynamicSharedMemorySize, GEMM_SMEM);
    const int ATTN_SMEM = 6*8192;                                 // 49152
    cudaFuncSetAttribute(attn_mma_kernel, cudaFuncAttributeMaxDynamicSharedMemorySize, ATTN_SMEM);

    const int CV_TOTAL = CV_XN + CV_W1 + CV_W2 + CV_W3;

    conv_all_kernel<<<(CV_TOTAL + 255)/256, 256>>>(x, meta, qw, kw, vw, ssm_in_w, projw);
    gemm_mma_kernel<<<dim3(DIMM/128, (BB*TE + 127)/128), 256, GEMM_SMEM>>>(
        p_xh, p_xl, p_wqh, p_wql, p_qkv, BB*TE, DIMM, 0);
    {
        int warps = BB*(NATTN + NKV + NKV)*TE;
        normrot_kernel<<<(warps*32 + 255)/256, 256>>>(qgain);
    }
    attn_mma_kernel<<<dim3((TE + 63)/64, NATTN, BB), 128, ATTN_SMEM>>>(attn_sc);
    gemm_mma_kernel<<<dim3((NSSM*DD)/128, (BB*TT)/128), 256, GEMM_SMEM>>>(
        p_xh, p_xl, p_wsh, p_wsl, p_ssmx, BB*TT, NSSM*DD, 1);
    dtbc_kernel<<<dim3(TT/64, NSSM, BB), 256>>>(dtw, dtb, Bw, Cw, logA);
    scan_kernel<<<BB*NSSM, 256>>>();
    ssmout_kernel<<<dim3(TT/64, NSSM, BB), 256>>>(Ow, ssm_sc);
    gemm_mma_kernel<<<dim3(DIMM/128, (BB*TT)/128), 256, GEMM_SMEM>>>(
        p_cth, p_ctl, p_wph, p_wpl, out, BB*TT, DIMM, 0);
}